// round 2
// baseline (speedup 1.0000x reference)
#include <cuda_runtime.h>
#include <mma.h>
#include <math.h>

using namespace nvcuda;

#define BATCH 16
#define SEQ   512
#define NTOK  (BATCH*SEQ)      // 8192
#define DC    1024
#define DP    64
#define NT    8
#define DH    4096

#define BM 128
#define BN 128
#define BK 32

// Scratch (static device globals — no runtime allocation).
// H holds raw (pre-bias, pre-gelu) GEMM1 output in gathered order, padded per tile
// to a multiple of BM rows so partial blocks never cross tile regions.
__device__ float g_H[(NTOK + NT*BM) * DH];
__device__ int   g_bucket[NT][NTOK];
__device__ int   g_counts[NT];
__device__ int   g_pp[NT];   // padded prefix (gathered H row offset per tile)

__device__ __forceinline__ float gelu_exact(float v) {
    return 0.5f * v * (1.0f + erff(v * 0.70710678118654752f));
}

__global__ void zero_counts_kernel() {
    if (threadIdx.x < NT) g_counts[threadIdx.x] = 0;
}

__global__ void finalize_kernel() {
    int off = 0;
    for (int t = 0; t < NT; t++) {
        g_pp[t] = off;
        off += ((g_counts[t] + BM - 1) / BM) * BM;
    }
}

// ---------------------------------------------------------------------------
// Routing: one warp per token. score[t] = pw * <pe[s], sign(psig[t])> +
//                                         cw * <x[token], sign(csig[t])>
// argmax (first max) -> bucket token.
// ---------------------------------------------------------------------------
__global__ void routing_kernel(const float* __restrict__ x,
                               const float* __restrict__ pe,
                               const float* __restrict__ pwp,
                               const float* __restrict__ cwp,
                               const float* __restrict__ pos_sigs,
                               const float* __restrict__ content_sigs)
{
    __shared__ float s_csig[NT][DC];   // 32 KB of sign values
    __shared__ float s_psig[NT][DP];   // 2 KB
    int tid = threadIdx.x;

    for (int i = tid; i < NT*DC; i += blockDim.x) {
        float v = content_sigs[i];
        ((float*)s_csig)[i] = (v > 0.f) ? 1.f : ((v < 0.f) ? -1.f : 0.f);
    }
    for (int i = tid; i < NT*DP; i += blockDim.x) {
        float v = pos_sigs[i];
        ((float*)s_psig)[i] = (v > 0.f) ? 1.f : ((v < 0.f) ? -1.f : 0.f);
    }
    __syncthreads();

    float pw = 1.f / (1.f + expf(-pwp[0]));
    float cw = 1.f / (1.f + expf(-cwp[0]));
    float tot = pw + cw;
    pw /= tot; cw /= tot;

    int token = (blockIdx.x * blockDim.x + tid) >> 5;
    int lane  = tid & 31;
    if (token >= NTOK) return;
    int s = token % SEQ;

    float acc[NT];
    #pragma unroll
    for (int t = 0; t < NT; t++) acc[t] = 0.f;

    const float* xr = x + (size_t)token * DC;
    for (int j = lane; j < DC; j += 32) {
        float xv = xr[j];
        #pragma unroll
        for (int t = 0; t < NT; t++) acc[t] += xv * s_csig[t][j];
    }
    #pragma unroll
    for (int t = 0; t < NT; t++) acc[t] *= cw;

    for (int j = lane; j < DP; j += 32) {
        float pv = pe[s*DP + j] * pw;
        #pragma unroll
        for (int t = 0; t < NT; t++) acc[t] += pv * s_psig[t][j];
    }

    #pragma unroll
    for (int t = 0; t < NT; t++) {
        #pragma unroll
        for (int o = 16; o > 0; o >>= 1)
            acc[t] += __shfl_xor_sync(0xffffffffu, acc[t], o);
    }

    if (lane == 0) {
        int best = 0; float bv = acc[0];
        #pragma unroll
        for (int t = 1; t < NT; t++)
            if (acc[t] > bv) { bv = acc[t]; best = t; }
        int pos = atomicAdd(&g_counts[best], 1);
        g_bucket[best][pos] = token;
    }
}

// ---------------------------------------------------------------------------
// GEMM1: H[gathered_row, :DH] = x[bucket rows] @ W1[t]   (raw, no bias/act)
// tf32 wmma, BM=128 BN=128 BK=32, 8 warps (4x2), direct global store.
// ---------------------------------------------------------------------------
__global__ void gemm1_kernel(const float* __restrict__ x,
                             const float* __restrict__ W1)
{
    const int t   = blockIdx.z;
    const int cnt = g_counts[t];
    const int row0 = blockIdx.y * BM;
    if (row0 >= cnt) return;
    const int n0 = blockIdx.x * BN;

    __shared__ float sA[BM][BK+4];   // 128x36
    __shared__ float sB[BK][BN+4];   // 32x132
    __shared__ int   rows[BM];

    int tid = threadIdx.x;
    if (tid < BM) {
        int r = row0 + tid;
        rows[tid] = (r < cnt) ? g_bucket[t][r] : -1;
    }
    __syncthreads();

    int wid = tid >> 5;
    int wm = wid >> 1, wn = wid & 1;   // 4 x 2 warp grid -> 32x64 per warp

    wmma::fragment<wmma::accumulator, 16, 16, 8, float> cf[2][4];
    #pragma unroll
    for (int i = 0; i < 2; i++)
        #pragma unroll
        for (int j = 0; j < 4; j++)
            wmma::fill_fragment(cf[i][j], 0.f);

    const float* Wt = W1 + (size_t)t * DC * DH;

    for (int k0 = 0; k0 < DC; k0 += BK) {
        // A tile: 128 rows x 32 cols = 1024 float4
        #pragma unroll
        for (int i = 0; i < 4; i++) {
            int idx = tid + i*256;
            int r = idx >> 3, c = idx & 7;
            int tok = rows[r];
            float4 v = make_float4(0.f, 0.f, 0.f, 0.f);
            if (tok >= 0)
                v = *(const float4*)(x + (size_t)tok*DC + k0 + c*4);
            *(float4*)&sA[r][c*4] = v;
        }
        // B tile: 32 rows x 128 cols = 1024 float4
        #pragma unroll
        for (int i = 0; i < 4; i++) {
            int idx = tid + i*256;
            int r = idx >> 5, c = idx & 31;
            float4 v = *(const float4*)(Wt + (size_t)(k0 + r)*DH + n0 + c*4);
            *(float4*)&sB[r][c*4] = v;
        }
        __syncthreads();

        #pragma unroll
        for (int kk = 0; kk < BK; kk += 8) {
            wmma::fragment<wmma::matrix_a, 16, 16, 8, wmma::precision::tf32, wmma::row_major> af[2];
            wmma::fragment<wmma::matrix_b, 16, 16, 8, wmma::precision::tf32, wmma::row_major> bf[4];
            #pragma unroll
            for (int i = 0; i < 2; i++) {
                wmma::load_matrix_sync(af[i], &sA[wm*32 + i*16][kk], BK+4);
                #pragma unroll
                for (int e = 0; e < af[i].num_elements; e++)
                    af[i].x[e] = wmma::__float_to_tf32(af[i].x[e]);
            }
            #pragma unroll
            for (int j = 0; j < 4; j++) {
                wmma::load_matrix_sync(bf[j], &sB[kk][wn*64 + j*16], BN+4);
                #pragma unroll
                for (int e = 0; e < bf[j].num_elements; e++)
                    bf[j].x[e] = wmma::__float_to_tf32(bf[j].x[e]);
            }
            #pragma unroll
            for (int i = 0; i < 2; i++)
                #pragma unroll
                for (int j = 0; j < 4; j++)
                    wmma::mma_sync(cf[i][j], af[i], bf[j], cf[i][j]);
        }
        __syncthreads();
    }

    // Direct store to gathered, padded H (rows contiguous within this block).
    float* Hb = g_H + (size_t)(g_pp[t] + row0) * DH + n0;
    #pragma unroll
    for (int i = 0; i < 2; i++)
        #pragma unroll
        for (int j = 0; j < 4; j++)
            wmma::store_matrix_sync(Hb + (size_t)(wm*32 + i*16)*DH + wn*64 + j*16,
                                    cf[i][j], DH, wmma::mem_row_major);
}

// ---------------------------------------------------------------------------
// GEMM2: out[token, :DC] = gelu(H + b1[t]) @ W2[t] + b2[t], scatter to tokens.
// bias+gelu fused into the A-load path.
// ---------------------------------------------------------------------------
__global__ void gemm2_kernel(const float* __restrict__ W2,
                             const float* __restrict__ b1,
                             const float* __restrict__ b2,
                             float* __restrict__ out)
{
    const int t   = blockIdx.z;
    const int cnt = g_counts[t];
    const int row0 = blockIdx.y * BM;
    if (row0 >= cnt) return;
    const int n0 = blockIdx.x * BN;

    // Union: (sA + sB) for mainloop, sC for epilogue staging.
    __shared__ __align__(16) char smem_raw[(BM*(BK+4) + BK*(BN+4)) * 4]; // 35328 B
    float (*sA)[BK+4] = (float(*)[BK+4])smem_raw;
    float (*sB)[BN+4] = (float(*)[BN+4])(smem_raw + BM*(BK+4)*4);
    float (*sC)[BN+4] = (float(*)[BN+4])smem_raw;   // 64 x 132 = 33792 B
    __shared__ int rows[BM];

    int tid = threadIdx.x;
    if (tid < BM) {
        int r = row0 + tid;
        rows[tid] = (r < cnt) ? g_bucket[t][r] : -1;
    }
    __syncthreads();

    int wid = tid >> 5;
    int wm = wid >> 1, wn = wid & 1;

    wmma::fragment<wmma::accumulator, 16, 16, 8, float> cf[2][4];
    #pragma unroll
    for (int i = 0; i < 2; i++)
        #pragma unroll
        for (int j = 0; j < 4; j++)
            wmma::fill_fragment(cf[i][j], 0.f);

    const float* Wt = W2 + (size_t)t * DH * DC;
    const float* b1t = b1 + (size_t)t * DH;
    const size_t hrow0 = (size_t)(g_pp[t] + row0);

    for (int k0 = 0; k0 < DH; k0 += BK) {
        // A tile from H with fused bias + exact gelu
        #pragma unroll
        for (int i = 0; i < 4; i++) {
            int idx = tid + i*256;
            int r = idx >> 3, c = idx & 7;
            float4 v = *(const float4*)(g_H + (hrow0 + r)*DH + k0 + c*4);
            float4 bb = *(const float4*)(b1t + k0 + c*4);
            v.x = gelu_exact(v.x + bb.x);
            v.y = gelu_exact(v.y + bb.y);
            v.z = gelu_exact(v.z + bb.z);
            v.w = gelu_exact(v.w + bb.w);
            *(float4*)&sA[r][c*4] = v;
        }
        // B tile from W2[t]
        #pragma unroll
        for (int i = 0; i < 4; i++) {
            int idx = tid + i*256;
            int r = idx >> 5, c = idx & 31;
            float4 v = *(const float4*)(Wt + (size_t)(k0 + r)*DC + n0 + c*4);
            *(float4*)&sB[r][c*4] = v;
        }
        __syncthreads();

        #pragma unroll
        for (int kk = 0; kk < BK; kk += 8) {
            wmma::fragment<wmma::matrix_a, 16, 16, 8, wmma::precision::tf32, wmma::row_major> af[2];
            wmma::fragment<wmma::matrix_b, 16, 16, 8, wmma::precision::tf32, wmma::row_major> bf[4];
            #pragma unroll
            for (int i = 0; i < 2; i++) {
                wmma::load_matrix_sync(af[i], &sA[wm*32 + i*16][kk], BK+4);
                #pragma unroll
                for (int e = 0; e < af[i].num_elements; e++)
                    af[i].x[e] = wmma::__float_to_tf32(af[i].x[e]);
            }
            #pragma unroll
            for (int j = 0; j < 4; j++) {
                wmma::load_matrix_sync(bf[j], &sB[kk][wn*64 + j*16], BN+4);
                #pragma unroll
                for (int e = 0; e < bf[j].num_elements; e++)
                    bf[j].x[e] = wmma::__float_to_tf32(bf[j].x[e]);
            }
            #pragma unroll
            for (int i = 0; i < 2; i++)
                #pragma unroll
                for (int j = 0; j < 4; j++)
                    wmma::mma_sync(cf[i][j], af[i], bf[j], cf[i][j]);
        }
        __syncthreads();
    }

    // Epilogue: stage 64 rows at a time through smem, add b2, scatter to tokens.
    #pragma unroll
    for (int half = 0; half < 2; half++) {
        if ((wm >> 1) == half) {
            int lm = wm & 1;   // 0/1 within this half
            #pragma unroll
            for (int i = 0; i < 2; i++)
                #pragma unroll
                for (int j = 0; j < 4; j++)
                    wmma::store_matrix_sync(&sC[lm*32 + i*16][wn*64 + j*16],
                                            cf[i][j], BN+4, wmma::mem_row_major);
        }
        __syncthreads();
        for (int idx = tid; idx < 64 * (BN/4); idx += 256) {
            int r  = idx >> 5;      // 0..63
            int c4 = idx & 31;
            int gr = half*64 + r;
            int tok = rows[gr];
            if (tok >= 0) {
                float4 v = *(float4*)&sC[r][c4*4];
                float4 bb = *(const float4*)(b2 + (size_t)t*DC + n0 + c4*4);
                v.x += bb.x; v.y += bb.y; v.z += bb.z; v.w += bb.w;
                *(float4*)(out + (size_t)tok*DC + n0 + c4*4) = v;
            }
        }
        __syncthreads();
    }
}

extern "C" void kernel_launch(void* const* d_in, const int* in_sizes, int n_in,
                              void* d_out, int out_size)
{
    const float* x            = (const float*)d_in[0];
    const float* pe           = (const float*)d_in[1];
    const float* pwp          = (const float*)d_in[2];
    const float* cwp          = (const float*)d_in[3];
    const float* pos_sigs     = (const float*)d_in[4];
    const float* content_sigs = (const float*)d_in[5];
    const float* W1           = (const float*)d_in[6];
    const float* b1           = (const float*)d_in[7];
    const float* W2           = (const float*)d_in[8];
    const float* b2           = (const float*)d_in[9];
    float* out = (float*)d_out;

    zero_counts_kernel<<<1, 32>>>();
    routing_kernel<<<NTOK/8, 256>>>(x, pe, pwp, cwp, pos_sigs, content_sigs);
    finalize_kernel<<<1, 1>>>();
    gemm1_kernel<<<dim3(DH/BN, NTOK/BM, NT), 256>>>(x, W1);
    gemm2_kernel<<<dim3(DC/BN, NTOK/BM, NT), 256>>>(W2, b1, b2, out);
}

// round 4
// speedup vs baseline: 2.1193x; 2.1193x over previous
#include <cuda_runtime.h>
#include <mma.h>
#include <math.h>
#include <cstdint>

using namespace nvcuda;

#define NTOK 8192
#define SEQ  512
#define DC   1024
#define DP   64
#define NT   8
#define DH   4096

#define BM 128
#define BN 128
#define BK 32
#define STAGES 3

#define A_ROWPAD (BK + 4)      // 36 floats = 144 B row stride (16B aligned)
#define B_ROWPAD (BN + 4)      // 132 floats = 528 B row stride (16B aligned)
#define A_STAGE_FLOATS (BM * A_ROWPAD)   // 4608
#define B_STAGE_FLOATS (BK * B_ROWPAD)   // 4224
#define STAGE_FLOATS (A_STAGE_FLOATS + B_STAGE_FLOATS)   // 8832
#define SMEM_DYN (STAGES * STAGE_FLOATS * 4)             // 105984 B
#define C_ROWPAD (BN + 4)

// ------------------------- device scratch (static) -------------------------
__device__ float g_H[(NTOK + NT*BM) * DH];   // gelu-activated H, gathered+padded
__device__ int   g_bucket[NT][NTOK];
__device__ int   g_counts[NT];
__device__ int   g_pp[NT];

// ------------------------------- helpers -----------------------------------
__device__ __forceinline__ uint32_t cvta_s(const void* p) {
    uint32_t a;
    asm("{ .reg .u64 t; cvta.to.shared.u64 t, %1; cvt.u32.u64 %0, t; }" : "=r"(a) : "l"(p));
    return a;
}
__device__ __forceinline__ void cp16(uint32_t dst, const void* src) {
    asm volatile("cp.async.cg.shared.global [%0], [%1], 16;" :: "r"(dst), "l"(src));
}
#define CP_COMMIT() asm volatile("cp.async.commit_group;" ::: "memory")
#define CP_WAIT(N)  asm volatile("cp.async.wait_group %0;" :: "n"(N) : "memory")

__device__ __forceinline__ float gelu_exact(float v) {
    return 0.5f * v * (1.0f + erff(v * 0.70710678118654752f));
}

// ------------------------------ small kernels ------------------------------
__global__ void zero_counts_kernel() {
    if (threadIdx.x < NT) g_counts[threadIdx.x] = 0;
}
__global__ void finalize_kernel() {
    int off = 0;
    for (int t = 0; t < NT; t++) {
        g_pp[t] = off;
        off += ((g_counts[t] + BM - 1) / BM) * BM;
    }
}

// ------------------------------ routing ------------------------------------
__global__ void routing_kernel(const float* __restrict__ x,
                               const float* __restrict__ pe,
                               const float* __restrict__ pwp,
                               const float* __restrict__ cwp,
                               const float* __restrict__ pos_sigs,
                               const float* __restrict__ content_sigs)
{
    __shared__ float s_csig[NT][DC];
    __shared__ float s_psig[NT][DP];
    int tid = threadIdx.x;
    for (int i = tid; i < NT*DC; i += blockDim.x) {
        float v = content_sigs[i];
        ((float*)s_csig)[i] = (v > 0.f) ? 1.f : ((v < 0.f) ? -1.f : 0.f);
    }
    for (int i = tid; i < NT*DP; i += blockDim.x) {
        float v = pos_sigs[i];
        ((float*)s_psig)[i] = (v > 0.f) ? 1.f : ((v < 0.f) ? -1.f : 0.f);
    }
    __syncthreads();

    float pw = 1.f / (1.f + expf(-pwp[0]));
    float cw = 1.f / (1.f + expf(-cwp[0]));
    float tot = pw + cw;
    pw /= tot; cw /= tot;

    int token = (blockIdx.x * blockDim.x + tid) >> 5;
    int lane  = tid & 31;
    if (token >= NTOK) return;
    int s = token % SEQ;

    float acc[NT];
    #pragma unroll
    for (int t = 0; t < NT; t++) acc[t] = 0.f;

    const float* xr = x + (size_t)token * DC;
    for (int j = lane; j < DC; j += 32) {
        float xv = xr[j];
        #pragma unroll
        for (int t = 0; t < NT; t++) acc[t] += xv * s_csig[t][j];
    }
    #pragma unroll
    for (int t = 0; t < NT; t++) acc[t] *= cw;
    for (int j = lane; j < DP; j += 32) {
        float pv = pe[s*DP + j] * pw;
        #pragma unroll
        for (int t = 0; t < NT; t++) acc[t] += pv * s_psig[t][j];
    }
    #pragma unroll
    for (int t = 0; t < NT; t++) {
        #pragma unroll
        for (int o = 16; o > 0; o >>= 1)
            acc[t] += __shfl_xor_sync(0xffffffffu, acc[t], o);
    }
    if (lane == 0) {
        int best = 0; float bv = acc[0];
        #pragma unroll
        for (int t = 1; t < NT; t++)
            if (acc[t] > bv) { bv = acc[t]; best = t; }
        int pos = atomicAdd(&g_counts[best], 1);
        g_bucket[best][pos] = token;
    }
}

// ===========================================================================
// Pipelined tf32 wmma GEMM core (shared by gemm1/gemm2 via template-ish macro)
// 256 threads, 8 warps (4m x 2n), 3-stage cp.async.
// ===========================================================================

// GEMM1: H[gathered] = gelu(x[bucket] @ W1[t] + b1[t])
__global__ __launch_bounds__(256) void gemm1_kernel(const float* __restrict__ x,
                                                    const float* __restrict__ W1,
                                                    const float* __restrict__ b1)
{
    const int t    = blockIdx.z;
    const int cnt  = g_counts[t];
    const int row0 = blockIdx.x * BM;
    if (row0 >= cnt) return;
    const int n0 = blockIdx.y * BN;

    extern __shared__ float smem[];
    __shared__ float s_bias[BN];

    const int tid = threadIdx.x;
    const int wid = tid >> 5;
    const int wm  = wid >> 1, wn = wid & 1;

    // --- per-thread load geometry (fixed rows across K iters) ---
    // A: idx = tid + i*256 -> r = tid>>3 + i*32, c = tid&7
    const int ac = tid & 7;
    const float* aptr[4];
    #pragma unroll
    for (int i = 0; i < 4; i++) {
        int r = (tid >> 3) + i * 32;
        int idx = row0 + r;
        if (idx > cnt - 1) idx = cnt - 1;            // clamp (dup rows, discarded later)
        aptr[i] = x + (size_t)g_bucket[t][idx] * DC + ac * 4;
    }
    // B: r = tid>>5 + i*8, c = tid&31
    const int bc = tid & 31;
    const float* Wt = W1 + (size_t)t * DC * DH;
    const float* bptr[4];
    #pragma unroll
    for (int i = 0; i < 4; i++)
        bptr[i] = Wt + (size_t)((tid >> 5) + i * 8) * DH + n0 + bc * 4;

    const uint32_t smem_u = cvta_s(smem);
    auto fill = [&](int j) {
        const int s = j % STAGES;
        const int k0 = j * BK;
        uint32_t aBase = smem_u + (uint32_t)(s * STAGE_FLOATS) * 4u;
        uint32_t bBase = aBase + A_STAGE_FLOATS * 4u;
        #pragma unroll
        for (int i = 0; i < 4; i++) {
            uint32_t off = (uint32_t)((tid >> 3) + i*32) * (A_ROWPAD*4u) + (uint32_t)ac * 16u;
            cp16(aBase + off, aptr[i] + k0);
        }
        #pragma unroll
        for (int i = 0; i < 4; i++) {
            uint32_t off = (uint32_t)((tid >> 5) + i*8) * (B_ROWPAD*4u) + (uint32_t)bc * 16u;
            cp16(bBase + off, bptr[i] + (size_t)k0 * DH);
        }
        CP_COMMIT();
    };

    wmma::fragment<wmma::accumulator, 16, 16, 8, float> cf[2][4];
    #pragma unroll
    for (int i = 0; i < 2; i++)
        #pragma unroll
        for (int j = 0; j < 4; j++)
            wmma::fill_fragment(cf[i][j], 0.f);

    const int NITER = DC / BK;   // 32
    fill(0); fill(1);

    for (int i = 0; i < NITER; i++) {
        if (i + 1 < NITER) { CP_WAIT(1); } else { CP_WAIT(0); }
        __syncthreads();
        if (i + 2 < NITER) fill(i + 2);

        const float* sA = smem + (i % STAGES) * STAGE_FLOATS;
        const float* sB = sA + A_STAGE_FLOATS;

        #pragma unroll
        for (int kk = 0; kk < BK; kk += 8) {
            wmma::fragment<wmma::matrix_a, 16, 16, 8, wmma::precision::tf32, wmma::row_major> af[2];
            wmma::fragment<wmma::matrix_b, 16, 16, 8, wmma::precision::tf32, wmma::row_major> bf[4];
            #pragma unroll
            for (int m = 0; m < 2; m++) {
                wmma::load_matrix_sync(af[m], sA + (wm*32 + m*16) * A_ROWPAD + kk, A_ROWPAD);
                #pragma unroll
                for (int e = 0; e < af[m].num_elements; e++)
                    af[m].x[e] = wmma::__float_to_tf32(af[m].x[e]);
            }
            #pragma unroll
            for (int n = 0; n < 4; n++) {
                wmma::load_matrix_sync(bf[n], sB + kk * B_ROWPAD + wn*64 + n*16, B_ROWPAD);
                #pragma unroll
                for (int e = 0; e < bf[n].num_elements; e++)
                    bf[n].x[e] = wmma::__float_to_tf32(bf[n].x[e]);
            }
            #pragma unroll
            for (int m = 0; m < 2; m++)
                #pragma unroll
                for (int n = 0; n < 4; n++)
                    wmma::mma_sync(cf[m][n], af[m], bf[n], cf[m][n]);
        }
        __syncthreads();
    }

    // --- epilogue: stage to smem, bias+gelu, coalesced store to g_H ---
    if (tid < BN) s_bias[tid] = b1[(size_t)t * DH + n0 + tid];
    float* sC = smem;   // 128 x C_ROWPAD fits in stage memory
    #pragma unroll
    for (int m = 0; m < 2; m++)
        #pragma unroll
        for (int n = 0; n < 4; n++)
            wmma::store_matrix_sync(sC + (wm*32 + m*16) * C_ROWPAD + wn*64 + n*16,
                                    cf[m][n], C_ROWPAD, wmma::mem_row_major);
    __syncthreads();

    float* Hbase = g_H + (size_t)(g_pp[t] + row0) * DH + n0;
    #pragma unroll
    for (int i = 0; i < 16; i++) {
        int idx = tid + i * 256;
        int r = idx >> 5, c4 = idx & 31;
        float4 v = *(float4*)(sC + r * C_ROWPAD + c4 * 4);
        v.x = gelu_exact(v.x + s_bias[c4*4 + 0]);
        v.y = gelu_exact(v.y + s_bias[c4*4 + 1]);
        v.z = gelu_exact(v.z + s_bias[c4*4 + 2]);
        v.w = gelu_exact(v.w + s_bias[c4*4 + 3]);
        *(float4*)(Hbase + (size_t)r * DH + c4 * 4) = v;
    }
}

// GEMM2: out[token] = H[gathered] @ W2[t] + b2[t]  (scatter)
__global__ __launch_bounds__(256) void gemm2_kernel(const float* __restrict__ W2,
                                                    const float* __restrict__ b2,
                                                    float* __restrict__ out)
{
    const int t    = blockIdx.z;
    const int cnt  = g_counts[t];
    const int row0 = blockIdx.x * BM;
    if (row0 >= cnt) return;
    const int n0 = blockIdx.y * BN;

    extern __shared__ float smem[];
    __shared__ float s_bias[BN];
    __shared__ int   s_rows[BM];

    const int tid = threadIdx.x;
    const int wid = tid >> 5;
    const int wm  = wid >> 1, wn = wid & 1;

    if (tid < BM) {
        int r = row0 + tid;
        s_rows[tid] = (r < cnt) ? g_bucket[t][r] : -1;
    }

    const int ac = tid & 7;
    const size_t hrow0 = (size_t)(g_pp[t] + row0);
    const float* aptr[4];
    #pragma unroll
    for (int i = 0; i < 4; i++)
        aptr[i] = g_H + (hrow0 + (tid >> 3) + i*32) * DH + ac * 4;

    const int bc = tid & 31;
    const float* Wt = W2 + (size_t)t * DH * DC;
    const float* bptr[4];
    #pragma unroll
    for (int i = 0; i < 4; i++)
        bptr[i] = Wt + (size_t)((tid >> 5) + i * 8) * DC + n0 + bc * 4;

    const uint32_t smem_u = cvta_s(smem);
    auto fill = [&](int j) {
        const int s = j % STAGES;
        const int k0 = j * BK;
        uint32_t aBase = smem_u + (uint32_t)(s * STAGE_FLOATS) * 4u;
        uint32_t bBase = aBase + A_STAGE_FLOATS * 4u;
        #pragma unroll
        for (int i = 0; i < 4; i++) {
            uint32_t off = (uint32_t)((tid >> 3) + i*32) * (A_ROWPAD*4u) + (uint32_t)ac * 16u;
            cp16(aBase + off, aptr[i] + k0);
        }
        #pragma unroll
        for (int i = 0; i < 4; i++) {
            uint32_t off = (uint32_t)((tid >> 5) + i*8) * (B_ROWPAD*4u) + (uint32_t)bc * 16u;
            cp16(bBase + off, bptr[i] + (size_t)k0 * DC);
        }
        CP_COMMIT();
    };

    wmma::fragment<wmma::accumulator, 16, 16, 8, float> cf[2][4];
    #pragma unroll
    for (int i = 0; i < 2; i++)
        #pragma unroll
        for (int j = 0; j < 4; j++)
            wmma::fill_fragment(cf[i][j], 0.f);

    const int NITER = DH / BK;   // 128
    fill(0); fill(1);

    for (int i = 0; i < NITER; i++) {
        if (i + 1 < NITER) { CP_WAIT(1); } else { CP_WAIT(0); }
        __syncthreads();
        if (i + 2 < NITER) fill(i + 2);

        const float* sA = smem + (i % STAGES) * STAGE_FLOATS;
        const float* sB = sA + A_STAGE_FLOATS;

        #pragma unroll
        for (int kk = 0; kk < BK; kk += 8) {
            wmma::fragment<wmma::matrix_a, 16, 16, 8, wmma::precision::tf32, wmma::row_major> af[2];
            wmma::fragment<wmma::matrix_b, 16, 16, 8, wmma::precision::tf32, wmma::row_major> bf[4];
            #pragma unroll
            for (int m = 0; m < 2; m++) {
                wmma::load_matrix_sync(af[m], sA + (wm*32 + m*16) * A_ROWPAD + kk, A_ROWPAD);
                #pragma unroll
                for (int e = 0; e < af[m].num_elements; e++)
                    af[m].x[e] = wmma::__float_to_tf32(af[m].x[e]);
            }
            #pragma unroll
            for (int n = 0; n < 4; n++) {
                wmma::load_matrix_sync(bf[n], sB + kk * B_ROWPAD + wn*64 + n*16, B_ROWPAD);
                #pragma unroll
                for (int e = 0; e < bf[n].num_elements; e++)
                    bf[n].x[e] = wmma::__float_to_tf32(bf[n].x[e]);
            }
            #pragma unroll
            for (int m = 0; m < 2; m++)
                #pragma unroll
                for (int n = 0; n < 4; n++)
                    wmma::mma_sync(cf[m][n], af[m], bf[n], cf[m][n]);
        }
        __syncthreads();
    }

    // --- epilogue: stage to smem, +b2, scatter to token rows ---
    if (tid < BN) s_bias[tid] = b2[(size_t)t * DC + n0 + tid];
    float* sC = smem;
    #pragma unroll
    for (int m = 0; m < 2; m++)
        #pragma unroll
        for (int n = 0; n < 4; n++)
            wmma::store_matrix_sync(sC + (wm*32 + m*16) * C_ROWPAD + wn*64 + n*16,
                                    cf[m][n], C_ROWPAD, wmma::mem_row_major);
    __syncthreads();

    #pragma unroll
    for (int i = 0; i < 16; i++) {
        int idx = tid + i * 256;
        int r = idx >> 5, c4 = idx & 31;
        int tok = s_rows[r];
        if (tok >= 0) {
            float4 v = *(float4*)(sC + r * C_ROWPAD + c4 * 4);
            v.x += s_bias[c4*4 + 0];
            v.y += s_bias[c4*4 + 1];
            v.z += s_bias[c4*4 + 2];
            v.w += s_bias[c4*4 + 3];
            *(float4*)(out + (size_t)tok * DC + n0 + c4 * 4) = v;
        }
    }
}

// ------------------------------- launcher ----------------------------------
extern "C" void kernel_launch(void* const* d_in, const int* in_sizes, int n_in,
                              void* d_out, int out_size)
{
    const float* x            = (const float*)d_in[0];
    const float* pe           = (const float*)d_in[1];
    const float* pwp          = (const float*)d_in[2];
    const float* cwp          = (const float*)d_in[3];
    const float* pos_sigs     = (const float*)d_in[4];
    const float* content_sigs = (const float*)d_in[5];
    const float* W1           = (const float*)d_in[6];
    const float* b1           = (const float*)d_in[7];
    const float* W2           = (const float*)d_in[8];
    const float* b2           = (const float*)d_in[9];
    float* out = (float*)d_out;

    static int attr_set = 0;
    if (!attr_set) {
        cudaFuncSetAttribute(gemm1_kernel, cudaFuncAttributeMaxDynamicSharedMemorySize, SMEM_DYN);
        cudaFuncSetAttribute(gemm2_kernel, cudaFuncAttributeMaxDynamicSharedMemorySize, SMEM_DYN);
        attr_set = 1;
    }

    zero_counts_kernel<<<1, 32>>>();
    routing_kernel<<<NTOK/8, 256>>>(x, pe, pwp, cwp, pos_sigs, content_sigs);
    finalize_kernel<<<1, 1>>>();
    gemm1_kernel<<<dim3(NTOK/BM, DH/BN, NT), 256, SMEM_DYN>>>(x, W1, b1);
    gemm2_kernel<<<dim3(NTOK/BM, DC/BN, NT), 256, SMEM_DYN>>>(W2, b2, out);
}

// round 5
// speedup vs baseline: 8.6803x; 4.0958x over previous
#include <cuda_runtime.h>
#include <cuda_fp16.h>
#include <mma.h>
#include <math.h>
#include <cstdint>

using namespace nvcuda;

#define NTOK 8192
#define SEQ  512
#define DC   1024
#define DP   64
#define NT   8
#define DH   4096

#define BM 128
#define BN 128
#define BK 32
#define STAGES 3

// fp16 smem tiles (halves)
#define A_ROWPAD_H 72                   // 32 data + 40 pad -> 144 B row (16B mult)
#define B_ROWPAD_H 136                  // 128 data + 8 pad -> 272 B row (16B mult)
#define A_STAGE_H (BM * A_ROWPAD_H)     // 9216 halves = 18432 B
#define B_STAGE_H (BK * B_ROWPAD_H)     // 4352 halves = 8704 B
#define STAGE_H   (A_STAGE_H + B_STAGE_H)
#define SMEM_DYN  (STAGES * STAGE_H * 2)   // 81408 B
#define C_ROWPAD  (BN + 4)

// ------------------------- device scratch (static) -------------------------
__device__ __half g_xh [NTOK * DC];
__device__ __half g_W1h[NT * DC * DH];
__device__ __half g_W2h[NT * DH * DC];
__device__ __half g_H  [(NTOK + NT*BM) * DH];   // gelu(h), gathered+padded, fp16
__device__ int    g_bucket[NT][NTOK];
__device__ int    g_counts[NT];
__device__ int    g_pp[NT];

// ------------------------------- helpers -----------------------------------
__device__ __forceinline__ uint32_t cvta_s(const void* p) {
    uint32_t a;
    asm("{ .reg .u64 t; cvta.to.shared.u64 t, %1; cvt.u32.u64 %0, t; }" : "=r"(a) : "l"(p));
    return a;
}
__device__ __forceinline__ void cp16(uint32_t dst, const void* src) {
    asm volatile("cp.async.cg.shared.global [%0], [%1], 16;" :: "r"(dst), "l"(src));
}
#define CP_COMMIT() asm volatile("cp.async.commit_group;" ::: "memory")
#define CP_WAIT(N)  asm volatile("cp.async.wait_group %0;" :: "n"(N) : "memory")

__device__ __forceinline__ float gelu_exact(float v) {
    return 0.5f * v * (1.0f + erff(v * 0.70710678118654752f));
}

// ------------------------------ small kernels ------------------------------
__global__ void zero_counts_kernel() {
    if (threadIdx.x < NT) g_counts[threadIdx.x] = 0;
}
__global__ void finalize_kernel() {
    int off = 0;
    for (int t = 0; t < NT; t++) {
        g_pp[t] = off;
        off += ((g_counts[t] + BM - 1) / BM) * BM;
    }
}

// fp32 -> fp16 bulk convert (vectorized, grid-stride)
__global__ __launch_bounds__(256) void convert_f2h_kernel(const float* __restrict__ src,
                                                          __half* __restrict__ dst, int n4) {
    int i = blockIdx.x * blockDim.x + threadIdx.x;
    int stride = gridDim.x * blockDim.x;
    for (; i < n4; i += stride) {
        float4 v = *(const float4*)(src + (size_t)i * 4);
        __half2 h0 = __floats2half2_rn(v.x, v.y);
        __half2 h1 = __floats2half2_rn(v.z, v.w);
        *(uint2*)(dst + (size_t)i * 4) = make_uint2(*(uint32_t*)&h0, *(uint32_t*)&h1);
    }
}

// ------------------------------ routing ------------------------------------
__global__ void routing_kernel(const float* __restrict__ x,
                               const float* __restrict__ pe,
                               const float* __restrict__ pwp,
                               const float* __restrict__ cwp,
                               const float* __restrict__ pos_sigs,
                               const float* __restrict__ content_sigs)
{
    __shared__ float s_csig[NT][DC];
    __shared__ float s_psig[NT][DP];
    int tid = threadIdx.x;
    for (int i = tid; i < NT*DC; i += blockDim.x) {
        float v = content_sigs[i];
        ((float*)s_csig)[i] = (v > 0.f) ? 1.f : ((v < 0.f) ? -1.f : 0.f);
    }
    for (int i = tid; i < NT*DP; i += blockDim.x) {
        float v = pos_sigs[i];
        ((float*)s_psig)[i] = (v > 0.f) ? 1.f : ((v < 0.f) ? -1.f : 0.f);
    }
    __syncthreads();

    float pw = 1.f / (1.f + expf(-pwp[0]));
    float cw = 1.f / (1.f + expf(-cwp[0]));
    float tot = pw + cw;
    pw /= tot; cw /= tot;

    int token = (blockIdx.x * blockDim.x + tid) >> 5;
    int lane  = tid & 31;
    if (token >= NTOK) return;
    int s = token % SEQ;

    float acc[NT];
    #pragma unroll
    for (int t = 0; t < NT; t++) acc[t] = 0.f;

    const float* xr = x + (size_t)token * DC;
    for (int j = lane; j < DC; j += 32) {
        float xv = xr[j];
        #pragma unroll
        for (int t = 0; t < NT; t++) acc[t] += xv * s_csig[t][j];
    }
    #pragma unroll
    for (int t = 0; t < NT; t++) acc[t] *= cw;
    for (int j = lane; j < DP; j += 32) {
        float pv = pe[s*DP + j] * pw;
        #pragma unroll
        for (int t = 0; t < NT; t++) acc[t] += pv * s_psig[t][j];
    }
    #pragma unroll
    for (int t = 0; t < NT; t++) {
        #pragma unroll
        for (int o = 16; o > 0; o >>= 1)
            acc[t] += __shfl_xor_sync(0xffffffffu, acc[t], o);
    }
    if (lane == 0) {
        int best = 0; float bv = acc[0];
        #pragma unroll
        for (int t = 1; t < NT; t++)
            if (acc[t] > bv) { bv = acc[t]; best = t; }
        int pos = atomicAdd(&g_counts[best], 1);
        g_bucket[best][pos] = token;
    }
}

// ===========================================================================
// fp16 HMMA GEMM, 256 threads (8 warps, 4m x 2n), 3-stage cp.async pipeline.
// ===========================================================================

// GEMM1: H[gathered] = gelu(x_h[bucket] @ W1h[t] + b1[t]),  H stored fp16
__global__ __launch_bounds__(256) void gemm1_kernel(const float* __restrict__ b1)
{
    const int t    = blockIdx.z;
    const int cnt  = g_counts[t];
    const int row0 = blockIdx.x * BM;
    if (row0 >= cnt) return;
    const int n0 = blockIdx.y * BN;

    extern __shared__ __half smem[];
    __shared__ float s_bias[BN];

    const int tid = threadIdx.x;
    const int wid = tid >> 5;
    const int wm  = wid >> 1, wn = wid & 1;

    // A: 128 rows x 64B; chunks/row = 4. Thread handles chunk tid and tid+256.
    const int ar = tid >> 2;               // row for first chunk (0..63)
    const int ac = tid & 3;                // 16B col within row
    const __half* aptr[2];
    #pragma unroll
    for (int i = 0; i < 2; i++) {
        int idx = row0 + ar + i * 64;
        if (idx > cnt - 1) idx = cnt - 1;  // clamp: dup rows, discarded at scatter
        aptr[i] = g_xh + (size_t)g_bucket[t][idx] * DC + ac * 8;
    }
    // B: 32 rows x 256B; chunks/row = 16. row = tid>>4 (+16), c16 = tid&15.
    const int br = tid >> 4;
    const int bc = tid & 15;
    const __half* Wt = g_W1h + (size_t)t * DC * DH + n0 + bc * 8;

    const uint32_t smem_u = cvta_s(smem);
    auto fill = [&](int j) {
        const int s = j % STAGES;
        const int k0 = j * BK;
        uint32_t aBase = smem_u + (uint32_t)(s * STAGE_H) * 2u;
        uint32_t bBase = aBase + A_STAGE_H * 2u;
        #pragma unroll
        for (int i = 0; i < 2; i++)
            cp16(aBase + (uint32_t)(ar + i*64) * (A_ROWPAD_H*2u) + (uint32_t)ac * 16u,
                 aptr[i] + k0);
        #pragma unroll
        for (int i = 0; i < 2; i++)
            cp16(bBase + (uint32_t)(br + i*16) * (B_ROWPAD_H*2u) + (uint32_t)bc * 16u,
                 Wt + (size_t)(k0 + br + i*16) * DH);
        CP_COMMIT();
    };

    wmma::fragment<wmma::accumulator, 16, 16, 16, float> cf[2][4];
    #pragma unroll
    for (int i = 0; i < 2; i++)
        #pragma unroll
        for (int j = 0; j < 4; j++)
            wmma::fill_fragment(cf[i][j], 0.f);

    const int NITER = DC / BK;   // 32
    fill(0); fill(1);

    for (int i = 0; i < NITER; i++) {
        if (i + 1 < NITER) { CP_WAIT(1); } else { CP_WAIT(0); }
        __syncthreads();
        if (i + 2 < NITER) fill(i + 2);

        const __half* sA = smem + (i % STAGES) * STAGE_H;
        const __half* sB = sA + A_STAGE_H;

        #pragma unroll
        for (int kk = 0; kk < BK; kk += 16) {
            wmma::fragment<wmma::matrix_a, 16, 16, 16, __half, wmma::row_major> af[2];
            wmma::fragment<wmma::matrix_b, 16, 16, 16, __half, wmma::row_major> bf[4];
            #pragma unroll
            for (int m = 0; m < 2; m++)
                wmma::load_matrix_sync(af[m], sA + (wm*32 + m*16) * A_ROWPAD_H + kk, A_ROWPAD_H);
            #pragma unroll
            for (int n = 0; n < 4; n++)
                wmma::load_matrix_sync(bf[n], sB + kk * B_ROWPAD_H + wn*64 + n*16, B_ROWPAD_H);
            #pragma unroll
            for (int m = 0; m < 2; m++)
                #pragma unroll
                for (int n = 0; n < 4; n++)
                    wmma::mma_sync(cf[m][n], af[m], bf[n], cf[m][n]);
        }
        __syncthreads();
    }

    // epilogue: stage float C to smem, bias+gelu, store fp16 H (coalesced 8B)
    if (tid < BN) s_bias[tid] = b1[(size_t)t * DH + n0 + tid];
    float* sC = (float*)smem;   // 128 x 132 floats = 67584 B <= 81408
    #pragma unroll
    for (int m = 0; m < 2; m++)
        #pragma unroll
        for (int n = 0; n < 4; n++)
            wmma::store_matrix_sync(sC + (wm*32 + m*16) * C_ROWPAD + wn*64 + n*16,
                                    cf[m][n], C_ROWPAD, wmma::mem_row_major);
    __syncthreads();

    __half* Hbase = g_H + (size_t)(g_pp[t] + row0) * DH + n0;
    #pragma unroll
    for (int i = 0; i < 16; i++) {
        int idx = tid + i * 256;
        int r = idx >> 5, c4 = idx & 31;
        float4 v = *(float4*)(sC + r * C_ROWPAD + c4 * 4);
        v.x = gelu_exact(v.x + s_bias[c4*4 + 0]);
        v.y = gelu_exact(v.y + s_bias[c4*4 + 1]);
        v.z = gelu_exact(v.z + s_bias[c4*4 + 2]);
        v.w = gelu_exact(v.w + s_bias[c4*4 + 3]);
        __half2 h0 = __floats2half2_rn(v.x, v.y);
        __half2 h1 = __floats2half2_rn(v.z, v.w);
        *(uint2*)(Hbase + (size_t)r * DH + c4 * 4) = make_uint2(*(uint32_t*)&h0, *(uint32_t*)&h1);
    }
}

// GEMM2: out[token] = H[gathered] @ W2h[t] + b2[t]  (fp32 out, scatter)
__global__ __launch_bounds__(256) void gemm2_kernel(const float* __restrict__ b2,
                                                    float* __restrict__ out)
{
    const int t    = blockIdx.z;
    const int cnt  = g_counts[t];
    const int row0 = blockIdx.x * BM;
    if (row0 >= cnt) return;
    const int n0 = blockIdx.y * BN;

    extern __shared__ __half smem[];
    __shared__ float s_bias[BN];
    __shared__ int   s_rows[BM];

    const int tid = threadIdx.x;
    const int wid = tid >> 5;
    const int wm  = wid >> 1, wn = wid & 1;

    if (tid < BM) {
        int r = row0 + tid;
        s_rows[tid] = (r < cnt) ? g_bucket[t][r] : -1;
    }

    const int ar = tid >> 2;
    const int ac = tid & 3;
    const size_t hrow0 = (size_t)(g_pp[t] + row0);
    const __half* aptr[2];
    #pragma unroll
    for (int i = 0; i < 2; i++)
        aptr[i] = g_H + (hrow0 + ar + i * 64) * DH + ac * 8;

    const int br = tid >> 4;
    const int bc = tid & 15;
    const __half* Wt = g_W2h + (size_t)t * DH * DC + n0 + bc * 8;

    const uint32_t smem_u = cvta_s(smem);
    auto fill = [&](int j) {
        const int s = j % STAGES;
        const int k0 = j * BK;
        uint32_t aBase = smem_u + (uint32_t)(s * STAGE_H) * 2u;
        uint32_t bBase = aBase + A_STAGE_H * 2u;
        #pragma unroll
        for (int i = 0; i < 2; i++)
            cp16(aBase + (uint32_t)(ar + i*64) * (A_ROWPAD_H*2u) + (uint32_t)ac * 16u,
                 aptr[i] + k0);
        #pragma unroll
        for (int i = 0; i < 2; i++)
            cp16(bBase + (uint32_t)(br + i*16) * (B_ROWPAD_H*2u) + (uint32_t)bc * 16u,
                 Wt + (size_t)(k0 + br + i*16) * DC);
        CP_COMMIT();
    };

    wmma::fragment<wmma::accumulator, 16, 16, 16, float> cf[2][4];
    #pragma unroll
    for (int i = 0; i < 2; i++)
        #pragma unroll
        for (int j = 0; j < 4; j++)
            wmma::fill_fragment(cf[i][j], 0.f);

    const int NITER = DH / BK;   // 128
    fill(0); fill(1);

    for (int i = 0; i < NITER; i++) {
        if (i + 1 < NITER) { CP_WAIT(1); } else { CP_WAIT(0); }
        __syncthreads();
        if (i + 2 < NITER) fill(i + 2);

        const __half* sA = smem + (i % STAGES) * STAGE_H;
        const __half* sB = sA + A_STAGE_H;

        #pragma unroll
        for (int kk = 0; kk < BK; kk += 16) {
            wmma::fragment<wmma::matrix_a, 16, 16, 16, __half, wmma::row_major> af[2];
            wmma::fragment<wmma::matrix_b, 16, 16, 16, __half, wmma::row_major> bf[4];
            #pragma unroll
            for (int m = 0; m < 2; m++)
                wmma::load_matrix_sync(af[m], sA + (wm*32 + m*16) * A_ROWPAD_H + kk, A_ROWPAD_H);
            #pragma unroll
            for (int n = 0; n < 4; n++)
                wmma::load_matrix_sync(bf[n], sB + kk * B_ROWPAD_H + wn*64 + n*16, B_ROWPAD_H);
            #pragma unroll
            for (int m = 0; m < 2; m++)
                #pragma unroll
                for (int n = 0; n < 4; n++)
                    wmma::mma_sync(cf[m][n], af[m], bf[n], cf[m][n]);
        }
        __syncthreads();
    }

    if (tid < BN) s_bias[tid] = b2[(size_t)t * DC + n0 + tid];
    float* sC = (float*)smem;
    #pragma unroll
    for (int m = 0; m < 2; m++)
        #pragma unroll
        for (int n = 0; n < 4; n++)
            wmma::store_matrix_sync(sC + (wm*32 + m*16) * C_ROWPAD + wn*64 + n*16,
                                    cf[m][n], C_ROWPAD, wmma::mem_row_major);
    __syncthreads();

    #pragma unroll
    for (int i = 0; i < 16; i++) {
        int idx = tid + i * 256;
        int r = idx >> 5, c4 = idx & 31;
        int tok = s_rows[r];
        if (tok >= 0) {
            float4 v = *(float4*)(sC + r * C_ROWPAD + c4 * 4);
            v.x += s_bias[c4*4 + 0];
            v.y += s_bias[c4*4 + 1];
            v.z += s_bias[c4*4 + 2];
            v.w += s_bias[c4*4 + 3];
            *(float4*)(out + (size_t)tok * DC + n0 + c4 * 4) = v;
        }
    }
}

// ------------------------------- launcher ----------------------------------
extern "C" void kernel_launch(void* const* d_in, const int* in_sizes, int n_in,
                              void* d_out, int out_size)
{
    const float* x            = (const float*)d_in[0];
    const float* pe           = (const float*)d_in[1];
    const float* pwp          = (const float*)d_in[2];
    const float* cwp          = (const float*)d_in[3];
    const float* pos_sigs     = (const float*)d_in[4];
    const float* content_sigs = (const float*)d_in[5];
    const float* W1           = (const float*)d_in[6];
    const float* b1           = (const float*)d_in[7];
    const float* W2           = (const float*)d_in[8];
    const float* b2           = (const float*)d_in[9];
    float* out = (float*)d_out;

    static int attr_set = 0;
    if (!attr_set) {
        cudaFuncSetAttribute(gemm1_kernel, cudaFuncAttributeMaxDynamicSharedMemorySize, SMEM_DYN);
        cudaFuncSetAttribute(gemm2_kernel, cudaFuncAttributeMaxDynamicSharedMemorySize, SMEM_DYN);
        attr_set = 1;
    }

    __half* xh;  cudaGetSymbolAddress((void**)&xh,  g_xh);
    __half* w1h; cudaGetSymbolAddress((void**)&w1h, g_W1h);
    __half* w2h; cudaGetSymbolAddress((void**)&w2h, g_W2h);

    zero_counts_kernel<<<1, 32>>>();
    routing_kernel<<<NTOK/8, 256>>>(x, pe, pwp, cwp, pos_sigs, content_sigs);
    finalize_kernel<<<1, 1>>>();

    convert_f2h_kernel<<<2048, 256>>>(x,  xh,  NTOK*DC/4);
    convert_f2h_kernel<<<8192, 256>>>(W1, w1h, NT*DC*DH/4);
    convert_f2h_kernel<<<8192, 256>>>(W2, w2h, NT*DH*DC/4);

    gemm1_kernel<<<dim3(NTOK/BM, DH/BN, NT), 256, SMEM_DYN>>>(b1);
    gemm2_kernel<<<dim3(NTOK/BM, DC/BN, NT), 256, SMEM_DYN>>>(b2, out);
}

// round 6
// speedup vs baseline: 9.2669x; 1.0676x over previous
#include <cuda_runtime.h>
#include <cuda_fp16.h>
#include <mma.h>
#include <math.h>
#include <cstdint>

using namespace nvcuda;

#define NTOK 8192
#define SEQ  512
#define DC   1024
#define DP   64
#define NT   8
#define DH   4096

#define BM 128
#define BN 128
#define BK 32
#define STAGES 4

// fp16 smem tiles
#define A_ROWPAD_H 40                    // 32 data + 8 pad halves -> 80 B rows
#define B_ROWPAD_H 136                   // 128 data + 8 pad halves -> 272 B rows
#define A_STAGE_H (BM * A_ROWPAD_H)      // 5120 halves = 10240 B
#define B_STAGE_H (BK * B_ROWPAD_H)      // 4352 halves = 8704 B
#define STAGE_H   (A_STAGE_H + B_STAGE_H)          // 9472 halves = 18944 B
#define SMEM_DYN  (STAGES * STAGE_H * 2)           // 75776 B
#define C_ROWPAD  (BN + 4)               // epilogue float staging (67584 B)

// ------------------------- device scratch (static) -------------------------
__device__ __half g_xh [NTOK * DC];
__device__ __half g_W1h[NT * DC * DH];
__device__ __half g_W2h[NT * DH * DC];
__device__ __half g_H  [(NTOK + NT*BM) * DH];
__device__ int    g_bucket[NT][NTOK];
__device__ int    g_counts[NT];
__device__ int    g_pp[NT];

// ------------------------------- helpers -----------------------------------
__device__ __forceinline__ uint32_t cvta_s(const void* p) {
    uint32_t a;
    asm("{ .reg .u64 t; cvta.to.shared.u64 t, %1; cvt.u32.u64 %0, t; }" : "=r"(a) : "l"(p));
    return a;
}
__device__ __forceinline__ void cp16(uint32_t dst, const void* src) {
    asm volatile("cp.async.cg.shared.global [%0], [%1], 16;" :: "r"(dst), "l"(src));
}
#define CP_COMMIT() asm volatile("cp.async.commit_group;" ::: "memory")
#define CP_WAIT(N)  asm volatile("cp.async.wait_group %0;" :: "n"(N) : "memory")

__device__ __forceinline__ float gelu_exact(float v) {
    return 0.5f * v * (1.0f + erff(v * 0.70710678118654752f));
}

// ------------------------------ small kernels ------------------------------
__global__ void zero_counts_kernel() {
    if (threadIdx.x < NT) g_counts[threadIdx.x] = 0;
}
__global__ void finalize_kernel() {
    int off = 0;
    for (int t = 0; t < NT; t++) {
        g_pp[t] = off;
        off += ((g_counts[t] + BM - 1) / BM) * BM;
    }
}

// fp32 -> fp16 bulk convert: 8 floats / thread-iter, 16B stores
__global__ __launch_bounds__(256) void convert_f2h_kernel(const float* __restrict__ src,
                                                          __half* __restrict__ dst, int n8) {
    int i = blockIdx.x * blockDim.x + threadIdx.x;
    int stride = gridDim.x * blockDim.x;
    for (; i < n8; i += stride) {
        float4 v0 = *(const float4*)(src + (size_t)i * 8);
        float4 v1 = *(const float4*)(src + (size_t)i * 8 + 4);
        __half2 h0 = __floats2half2_rn(v0.x, v0.y);
        __half2 h1 = __floats2half2_rn(v0.z, v0.w);
        __half2 h2 = __floats2half2_rn(v1.x, v1.y);
        __half2 h3 = __floats2half2_rn(v1.z, v1.w);
        *(uint4*)(dst + (size_t)i * 8) =
            make_uint4(*(uint32_t*)&h0, *(uint32_t*)&h1, *(uint32_t*)&h2, *(uint32_t*)&h3);
    }
}

// ------------------------------ routing ------------------------------------
__global__ void routing_kernel(const float* __restrict__ x,
                               const float* __restrict__ pe,
                               const float* __restrict__ pwp,
                               const float* __restrict__ cwp,
                               const float* __restrict__ pos_sigs,
                               const float* __restrict__ content_sigs)
{
    __shared__ float s_csig[NT][DC];
    __shared__ float s_psig[NT][DP];
    int tid = threadIdx.x;
    for (int i = tid; i < NT*DC; i += blockDim.x) {
        float v = content_sigs[i];
        ((float*)s_csig)[i] = (v > 0.f) ? 1.f : ((v < 0.f) ? -1.f : 0.f);
    }
    for (int i = tid; i < NT*DP; i += blockDim.x) {
        float v = pos_sigs[i];
        ((float*)s_psig)[i] = (v > 0.f) ? 1.f : ((v < 0.f) ? -1.f : 0.f);
    }
    __syncthreads();

    float pw = 1.f / (1.f + expf(-pwp[0]));
    float cw = 1.f / (1.f + expf(-cwp[0]));
    float tot = pw + cw;
    pw /= tot; cw /= tot;

    int token = (blockIdx.x * blockDim.x + tid) >> 5;
    int lane  = tid & 31;
    if (token >= NTOK) return;
    int s = token % SEQ;

    float acc[NT];
    #pragma unroll
    for (int t = 0; t < NT; t++) acc[t] = 0.f;

    const float* xr = x + (size_t)token * DC;
    for (int j = lane; j < DC; j += 32) {
        float xv = xr[j];
        #pragma unroll
        for (int t = 0; t < NT; t++) acc[t] += xv * s_csig[t][j];
    }
    #pragma unroll
    for (int t = 0; t < NT; t++) acc[t] *= cw;
    for (int j = lane; j < DP; j += 32) {
        float pv = pe[s*DP + j] * pw;
        #pragma unroll
        for (int t = 0; t < NT; t++) acc[t] += pv * s_psig[t][j];
    }
    #pragma unroll
    for (int t = 0; t < NT; t++) {
        #pragma unroll
        for (int o = 16; o > 0; o >>= 1)
            acc[t] += __shfl_xor_sync(0xffffffffu, acc[t], o);
    }
    if (lane == 0) {
        int best = 0; float bv = acc[0];
        #pragma unroll
        for (int t = 1; t < NT; t++)
            if (acc[t] > bv) { bv = acc[t]; best = t; }
        int pos = atomicAdd(&g_counts[best], 1);
        g_bucket[best][pos] = token;
    }
}

// ===========================================================================
// fp16 HMMA GEMM: 128 threads (4 warps, 2x2), warp tile 64x64, 4-stage
// cp.async, single barrier per K-iter, 2 CTAs/SM.
// ===========================================================================

// GEMM1: H[gathered] = gelu(x_h[bucket] @ W1h[t] + b1[t]),  H fp16
__global__ __launch_bounds__(128, 2) void gemm1_kernel(const float* __restrict__ b1)
{
    const int t    = blockIdx.z;
    const int cnt  = g_counts[t];
    const int row0 = blockIdx.x * BM;
    if (row0 >= cnt) return;
    const int n0 = blockIdx.y * BN;

    extern __shared__ __half smem[];
    __shared__ float s_bias[BN];

    const int tid = threadIdx.x;
    const int wid = tid >> 5;
    const int wm  = wid >> 1, wn = wid & 1;    // 2x2 warps, 64x64 each

    // A loads: 128 rows x 64B, 4 chunks/row. thread -> (row base tid>>2, chunk tid&3)
    const int ar = tid >> 2;                   // 0..31
    const int ac = tid & 3;
    const __half* aptr[4];
    #pragma unroll
    for (int i = 0; i < 4; i++) {
        int idx = row0 + ar + i * 32;
        if (idx > cnt - 1) idx = cnt - 1;      // clamp: dup rows, masked at scatter
        aptr[i] = g_xh + (size_t)g_bucket[t][idx] * DC + ac * 8;
    }
    // B loads: 32 rows x 256B, 16 chunks/row. thread -> (row tid>>4, chunk tid&15)
    const int br = tid >> 4;                   // 0..7
    const int bc = tid & 15;
    const __half* Wt = g_W1h + (size_t)t * DC * DH + n0 + bc * 8;

    const uint32_t smem_u = cvta_s(smem);
    auto fill = [&](int j) {
        const int s = j % STAGES;
        const int k0 = j * BK;
        uint32_t aBase = smem_u + (uint32_t)(s * STAGE_H) * 2u;
        uint32_t bBase = aBase + A_STAGE_H * 2u;
        #pragma unroll
        for (int i = 0; i < 4; i++)
            cp16(aBase + (uint32_t)(ar + i*32) * (A_ROWPAD_H*2u) + (uint32_t)ac * 16u,
                 aptr[i] + k0);
        #pragma unroll
        for (int i = 0; i < 4; i++)
            cp16(bBase + (uint32_t)(br + i*8) * (B_ROWPAD_H*2u) + (uint32_t)bc * 16u,
                 Wt + (size_t)(k0 + br + i*8) * DH);
        CP_COMMIT();
    };

    wmma::fragment<wmma::accumulator, 16, 16, 16, float> cf[4][4];
    #pragma unroll
    for (int i = 0; i < 4; i++)
        #pragma unroll
        for (int j = 0; j < 4; j++)
            wmma::fill_fragment(cf[i][j], 0.f);

    const int NITER = DC / BK;   // 32
    fill(0); fill(1); fill(2);

    for (int i = 0; i < NITER; i++) {
        if      (i + 3 <= NITER) { CP_WAIT(2); }
        else if (i + 2 == NITER) { CP_WAIT(1); }
        else                     { CP_WAIT(0); }
        __syncthreads();                       // also retires stage (i-1)%4 compute
        if (i + 3 < NITER) fill(i + 3);

        const __half* sA = smem + (i % STAGES) * STAGE_H;
        const __half* sB = sA + A_STAGE_H;

        #pragma unroll
        for (int kk = 0; kk < BK; kk += 16) {
            wmma::fragment<wmma::matrix_a, 16, 16, 16, __half, wmma::row_major> af[4];
            wmma::fragment<wmma::matrix_b, 16, 16, 16, __half, wmma::row_major> bf[4];
            #pragma unroll
            for (int m = 0; m < 4; m++)
                wmma::load_matrix_sync(af[m], sA + (wm*64 + m*16) * A_ROWPAD_H + kk, A_ROWPAD_H);
            #pragma unroll
            for (int n = 0; n < 4; n++)
                wmma::load_matrix_sync(bf[n], sB + kk * B_ROWPAD_H + wn*64 + n*16, B_ROWPAD_H);
            #pragma unroll
            for (int m = 0; m < 4; m++)
                #pragma unroll
                for (int n = 0; n < 4; n++)
                    wmma::mma_sync(cf[m][n], af[m], bf[n], cf[m][n]);
        }
    }

    // epilogue: stage float C, bias+gelu, fp16 store to g_H
    if (tid < BN) s_bias[tid] = b1[(size_t)t * DH + n0 + tid];
    __syncthreads();                           // all compute done before overlay
    float* sC = (float*)smem;                  // 128 x 132 floats = 67584 B
    #pragma unroll
    for (int m = 0; m < 4; m++)
        #pragma unroll
        for (int n = 0; n < 4; n++)
            wmma::store_matrix_sync(sC + (wm*64 + m*16) * C_ROWPAD + wn*64 + n*16,
                                    cf[m][n], C_ROWPAD, wmma::mem_row_major);
    __syncthreads();

    __half* Hbase = g_H + (size_t)(g_pp[t] + row0) * DH + n0;
    #pragma unroll
    for (int i = 0; i < 32; i++) {
        int idx = tid + i * 128;
        int r = idx >> 5, c4 = idx & 31;
        float4 v = *(float4*)(sC + r * C_ROWPAD + c4 * 4);
        v.x = gelu_exact(v.x + s_bias[c4*4 + 0]);
        v.y = gelu_exact(v.y + s_bias[c4*4 + 1]);
        v.z = gelu_exact(v.z + s_bias[c4*4 + 2]);
        v.w = gelu_exact(v.w + s_bias[c4*4 + 3]);
        __half2 h0 = __floats2half2_rn(v.x, v.y);
        __half2 h1 = __floats2half2_rn(v.z, v.w);
        *(uint2*)(Hbase + (size_t)r * DH + c4 * 4) = make_uint2(*(uint32_t*)&h0, *(uint32_t*)&h1);
    }
}

// GEMM2: out[token] = H[gathered] @ W2h[t] + b2[t]  (fp32 scatter)
__global__ __launch_bounds__(128, 2) void gemm2_kernel(const float* __restrict__ b2,
                                                       float* __restrict__ out)
{
    const int t    = blockIdx.z;
    const int cnt  = g_counts[t];
    const int row0 = blockIdx.x * BM;
    if (row0 >= cnt) return;
    const int n0 = blockIdx.y * BN;

    extern __shared__ __half smem[];
    __shared__ float s_bias[BN];
    __shared__ int   s_rows[BM];

    const int tid = threadIdx.x;
    const int wid = tid >> 5;
    const int wm  = wid >> 1, wn = wid & 1;

    if (tid < BM) {
        int r = row0 + tid;
        s_rows[tid] = (r < cnt) ? g_bucket[t][r] : -1;
    }

    const int ar = tid >> 2;
    const int ac = tid & 3;
    const size_t hrow0 = (size_t)(g_pp[t] + row0);
    const __half* aptr[4];
    #pragma unroll
    for (int i = 0; i < 4; i++)
        aptr[i] = g_H + (hrow0 + ar + i * 32) * DH + ac * 8;

    const int br = tid >> 4;
    const int bc = tid & 15;
    const __half* Wt = g_W2h + (size_t)t * DH * DC + n0 + bc * 8;

    const uint32_t smem_u = cvta_s(smem);
    auto fill = [&](int j) {
        const int s = j % STAGES;
        const int k0 = j * BK;
        uint32_t aBase = smem_u + (uint32_t)(s * STAGE_H) * 2u;
        uint32_t bBase = aBase + A_STAGE_H * 2u;
        #pragma unroll
        for (int i = 0; i < 4; i++)
            cp16(aBase + (uint32_t)(ar + i*32) * (A_ROWPAD_H*2u) + (uint32_t)ac * 16u,
                 aptr[i] + k0);
        #pragma unroll
        for (int i = 0; i < 4; i++)
            cp16(bBase + (uint32_t)(br + i*8) * (B_ROWPAD_H*2u) + (uint32_t)bc * 16u,
                 Wt + (size_t)(k0 + br + i*8) * DC);
        CP_COMMIT();
    };

    wmma::fragment<wmma::accumulator, 16, 16, 16, float> cf[4][4];
    #pragma unroll
    for (int i = 0; i < 4; i++)
        #pragma unroll
        for (int j = 0; j < 4; j++)
            wmma::fill_fragment(cf[i][j], 0.f);

    const int NITER = DH / BK;   // 128
    fill(0); fill(1); fill(2);

    for (int i = 0; i < NITER; i++) {
        if      (i + 3 <= NITER) { CP_WAIT(2); }
        else if (i + 2 == NITER) { CP_WAIT(1); }
        else                     { CP_WAIT(0); }
        __syncthreads();
        if (i + 3 < NITER) fill(i + 3);

        const __half* sA = smem + (i % STAGES) * STAGE_H;
        const __half* sB = sA + A_STAGE_H;

        #pragma unroll
        for (int kk = 0; kk < BK; kk += 16) {
            wmma::fragment<wmma::matrix_a, 16, 16, 16, __half, wmma::row_major> af[4];
            wmma::fragment<wmma::matrix_b, 16, 16, 16, __half, wmma::row_major> bf[4];
            #pragma unroll
            for (int m = 0; m < 4; m++)
                wmma::load_matrix_sync(af[m], sA + (wm*64 + m*16) * A_ROWPAD_H + kk, A_ROWPAD_H);
            #pragma unroll
            for (int n = 0; n < 4; n++)
                wmma::load_matrix_sync(bf[n], sB + kk * B_ROWPAD_H + wn*64 + n*16, B_ROWPAD_H);
            #pragma unroll
            for (int m = 0; m < 4; m++)
                #pragma unroll
                for (int n = 0; n < 4; n++)
                    wmma::mma_sync(cf[m][n], af[m], bf[n], cf[m][n]);
        }
    }

    if (tid < BN) s_bias[tid] = b2[(size_t)t * DC + n0 + tid];
    __syncthreads();
    float* sC = (float*)smem;
    #pragma unroll
    for (int m = 0; m < 4; m++)
        #pragma unroll
        for (int n = 0; n < 4; n++)
            wmma::store_matrix_sync(sC + (wm*64 + m*16) * C_ROWPAD + wn*64 + n*16,
                                    cf[m][n], C_ROWPAD, wmma::mem_row_major);
    __syncthreads();

    #pragma unroll
    for (int i = 0; i < 32; i++) {
        int idx = tid + i * 128;
        int r = idx >> 5, c4 = idx & 31;
        int tok = s_rows[r];
        if (tok >= 0) {
            float4 v = *(float4*)(sC + r * C_ROWPAD + c4 * 4);
            v.x += s_bias[c4*4 + 0];
            v.y += s_bias[c4*4 + 1];
            v.z += s_bias[c4*4 + 2];
            v.w += s_bias[c4*4 + 3];
            *(float4*)(out + (size_t)tok * DC + n0 + c4 * 4) = v;
        }
    }
}

// ------------------------------- launcher ----------------------------------
extern "C" void kernel_launch(void* const* d_in, const int* in_sizes, int n_in,
                              void* d_out, int out_size)
{
    const float* x            = (const float*)d_in[0];
    const float* pe           = (const float*)d_in[1];
    const float* pwp          = (const float*)d_in[2];
    const float* cwp          = (const float*)d_in[3];
    const float* pos_sigs     = (const float*)d_in[4];
    const float* content_sigs = (const float*)d_in[5];
    const float* W1           = (const float*)d_in[6];
    const float* b1           = (const float*)d_in[7];
    const float* W2           = (const float*)d_in[8];
    const float* b2           = (const float*)d_in[9];
    float* out = (float*)d_out;

    static int attr_set = 0;
    if (!attr_set) {
        cudaFuncSetAttribute(gemm1_kernel, cudaFuncAttributeMaxDynamicSharedMemorySize, SMEM_DYN);
        cudaFuncSetAttribute(gemm2_kernel, cudaFuncAttributeMaxDynamicSharedMemorySize, SMEM_DYN);
        attr_set = 1;
    }

    __half* xh;  cudaGetSymbolAddress((void**)&xh,  g_xh);
    __half* w1h; cudaGetSymbolAddress((void**)&w1h, g_W1h);
    __half* w2h; cudaGetSymbolAddress((void**)&w2h, g_W2h);

    zero_counts_kernel<<<1, 32>>>();
    routing_kernel<<<NTOK/8, 256>>>(x, pe, pwp, cwp, pos_sigs, content_sigs);
    finalize_kernel<<<1, 1>>>();

    convert_f2h_kernel<<<1024, 256>>>(x,  xh,  NTOK*DC/8);
    convert_f2h_kernel<<<4096, 256>>>(W1, w1h, NT*DC*DH/8);
    convert_f2h_kernel<<<4096, 256>>>(W2, w2h, NT*DH*DC/8);

    gemm1_kernel<<<dim3(NTOK/BM, DH/BN, NT), 128, SMEM_DYN>>>(b1);
    gemm2_kernel<<<dim3(NTOK/BM, DC/BN, NT), 128, SMEM_DYN>>>(b2, out);
}

// round 7
// speedup vs baseline: 9.5149x; 1.0268x over previous
#include <cuda_runtime.h>
#include <cuda_fp16.h>
#include <mma.h>
#include <math.h>
#include <cstdint>

using namespace nvcuda;

#define NTOK 8192
#define SEQ  512
#define DC   1024
#define DP   64
#define NT   8
#define DH   4096

#define BM 128
#define BN 128
#define BK 32
#define STAGES 4

#define A_ROWPAD_H 40
#define B_ROWPAD_H 136
#define A_STAGE_H (BM * A_ROWPAD_H)
#define B_STAGE_H (BK * B_ROWPAD_H)
#define STAGE_H   (A_STAGE_H + B_STAGE_H)
#define SMEM_DYN  (STAGES * STAGE_H * 2)
#define C_ROWPAD  (BN + 4)

// ------------------------- device scratch (static) -------------------------
__device__ __half g_xh [NTOK * DC];
__device__ __half g_W1h[NT * DC * DH];
__device__ __half g_W2h[NT * DH * DC];
__device__ __half g_H  [(NTOK + NT*BM) * DH];
__device__ int    g_bucket[NT][NTOK];
__device__ int    g_counts[NT];
__device__ int    g_pp[NT];

// ------------------------------- helpers -----------------------------------
__device__ __forceinline__ uint32_t cvta_s(const void* p) {
    uint32_t a;
    asm("{ .reg .u64 t; cvta.to.shared.u64 t, %1; cvt.u32.u64 %0, t; }" : "=r"(a) : "l"(p));
    return a;
}
__device__ __forceinline__ void cp16(uint32_t dst, const void* src) {
    asm volatile("cp.async.cg.shared.global [%0], [%1], 16;" :: "r"(dst), "l"(src));
}
#define CP_COMMIT() asm volatile("cp.async.commit_group;" ::: "memory")
#define CP_WAIT(N)  asm volatile("cp.async.wait_group %0;" :: "n"(N) : "memory")

__device__ __forceinline__ float gelu_exact(float v) {
    return 0.5f * v * (1.0f + erff(v * 0.70710678118654752f));
}

// ------------------------------ small kernels ------------------------------
__global__ void zero_counts_kernel() {
    if (threadIdx.x < NT) g_counts[threadIdx.x] = 0;
}
__global__ void finalize_kernel() {
    int off = 0;
    for (int t = 0; t < NT; t++) {
        g_pp[t] = off;
        off += ((g_counts[t] + BM - 1) / BM) * BM;
    }
}

// fp32 -> fp16 convert: block-tiled, 8192 floats per 256-thread block.
// 8 independent coalesced 16B loads per thread (MLP=8), 8B stores.
__global__ __launch_bounds__(256) void convert_f2h_kernel(const float* __restrict__ src,
                                                          __half* __restrict__ dst) {
    const size_t base = (size_t)blockIdx.x * 8192;
    const int tid = threadIdx.x;
    float4 v[8];
    #pragma unroll
    for (int i = 0; i < 8; i++)
        v[i] = *(const float4*)(src + base + (size_t)(i*256 + tid) * 4);
    #pragma unroll
    for (int i = 0; i < 8; i++) {
        __half2 h0 = __floats2half2_rn(v[i].x, v[i].y);
        __half2 h1 = __floats2half2_rn(v[i].z, v[i].w);
        *(uint2*)(dst + base + (size_t)(i*256 + tid) * 4) =
            make_uint2(*(uint32_t*)&h0, *(uint32_t*)&h1);
    }
}

// ------------------- routing (+ fused x -> fp16 convert) -------------------
__global__ void routing_kernel(const float* __restrict__ x,
                               const float* __restrict__ pe,
                               const float* __restrict__ pwp,
                               const float* __restrict__ cwp,
                               const float* __restrict__ pos_sigs,
                               const float* __restrict__ content_sigs)
{
    __shared__ float s_csig[NT][DC];
    __shared__ float s_psig[NT][DP];
    int tid = threadIdx.x;
    for (int i = tid; i < NT*DC; i += blockDim.x) {
        float v = content_sigs[i];
        ((float*)s_csig)[i] = (v > 0.f) ? 1.f : ((v < 0.f) ? -1.f : 0.f);
    }
    for (int i = tid; i < NT*DP; i += blockDim.x) {
        float v = pos_sigs[i];
        ((float*)s_psig)[i] = (v > 0.f) ? 1.f : ((v < 0.f) ? -1.f : 0.f);
    }
    __syncthreads();

    float pw = 1.f / (1.f + expf(-pwp[0]));
    float cw = 1.f / (1.f + expf(-cwp[0]));
    float tot = pw + cw;
    pw /= tot; cw /= tot;

    int token = (blockIdx.x * blockDim.x + tid) >> 5;
    int lane  = tid & 31;
    if (token >= NTOK) return;
    int s = token % SEQ;

    float acc[NT];
    #pragma unroll
    for (int t = 0; t < NT; t++) acc[t] = 0.f;

    const float* xr = x + (size_t)token * DC;
    __half* xh = g_xh + (size_t)token * DC;
    for (int j = lane; j < DC; j += 32) {
        float xv = xr[j];
        xh[j] = __float2half_rn(xv);            // fused convert
        #pragma unroll
        for (int t = 0; t < NT; t++) acc[t] += xv * s_csig[t][j];
    }
    #pragma unroll
    for (int t = 0; t < NT; t++) acc[t] *= cw;
    for (int j = lane; j < DP; j += 32) {
        float pv = pe[s*DP + j] * pw;
        #pragma unroll
        for (int t = 0; t < NT; t++) acc[t] += pv * s_psig[t][j];
    }
    #pragma unroll
    for (int t = 0; t < NT; t++) {
        #pragma unroll
        for (int o = 16; o > 0; o >>= 1)
            acc[t] += __shfl_xor_sync(0xffffffffu, acc[t], o);
    }
    if (lane == 0) {
        int best = 0; float bv = acc[0];
        #pragma unroll
        for (int t = 1; t < NT; t++)
            if (acc[t] > bv) { bv = acc[t]; best = t; }
        int pos = atomicAdd(&g_counts[best], 1);
        g_bucket[best][pos] = token;
    }
}

// ===========================================================================
// fp16 HMMA GEMMs (unchanged from round 6): 128 threads, 2x2 warps of 64x64,
// 4-stage cp.async, one barrier per K-iter, 2 CTAs/SM.
// ===========================================================================

__global__ __launch_bounds__(128, 2) void gemm1_kernel(const float* __restrict__ b1)
{
    const int t    = blockIdx.z;
    const int cnt  = g_counts[t];
    const int row0 = blockIdx.x * BM;
    if (row0 >= cnt) return;
    const int n0 = blockIdx.y * BN;

    extern __shared__ __half smem[];
    __shared__ float s_bias[BN];

    const int tid = threadIdx.x;
    const int wid = tid >> 5;
    const int wm  = wid >> 1, wn = wid & 1;

    const int ar = tid >> 2;
    const int ac = tid & 3;
    const __half* aptr[4];
    #pragma unroll
    for (int i = 0; i < 4; i++) {
        int idx = row0 + ar + i * 32;
        if (idx > cnt - 1) idx = cnt - 1;
        aptr[i] = g_xh + (size_t)g_bucket[t][idx] * DC + ac * 8;
    }
    const int br = tid >> 4;
    const int bc = tid & 15;
    const __half* Wt = g_W1h + (size_t)t * DC * DH + n0 + bc * 8;

    const uint32_t smem_u = cvta_s(smem);
    auto fill = [&](int j) {
        const int s = j % STAGES;
        const int k0 = j * BK;
        uint32_t aBase = smem_u + (uint32_t)(s * STAGE_H) * 2u;
        uint32_t bBase = aBase + A_STAGE_H * 2u;
        #pragma unroll
        for (int i = 0; i < 4; i++)
            cp16(aBase + (uint32_t)(ar + i*32) * (A_ROWPAD_H*2u) + (uint32_t)ac * 16u,
                 aptr[i] + k0);
        #pragma unroll
        for (int i = 0; i < 4; i++)
            cp16(bBase + (uint32_t)(br + i*8) * (B_ROWPAD_H*2u) + (uint32_t)bc * 16u,
                 Wt + (size_t)(k0 + br + i*8) * DH);
        CP_COMMIT();
    };

    wmma::fragment<wmma::accumulator, 16, 16, 16, float> cf[4][4];
    #pragma unroll
    for (int i = 0; i < 4; i++)
        #pragma unroll
        for (int j = 0; j < 4; j++)
            wmma::fill_fragment(cf[i][j], 0.f);

    const int NITER = DC / BK;
    fill(0); fill(1); fill(2);

    for (int i = 0; i < NITER; i++) {
        if      (i + 3 <= NITER) { CP_WAIT(2); }
        else if (i + 2 == NITER) { CP_WAIT(1); }
        else                     { CP_WAIT(0); }
        __syncthreads();
        if (i + 3 < NITER) fill(i + 3);

        const __half* sA = smem + (i % STAGES) * STAGE_H;
        const __half* sB = sA + A_STAGE_H;

        #pragma unroll
        for (int kk = 0; kk < BK; kk += 16) {
            wmma::fragment<wmma::matrix_a, 16, 16, 16, __half, wmma::row_major> af[4];
            wmma::fragment<wmma::matrix_b, 16, 16, 16, __half, wmma::row_major> bf[4];
            #pragma unroll
            for (int m = 0; m < 4; m++)
                wmma::load_matrix_sync(af[m], sA + (wm*64 + m*16) * A_ROWPAD_H + kk, A_ROWPAD_H);
            #pragma unroll
            for (int n = 0; n < 4; n++)
                wmma::load_matrix_sync(bf[n], sB + kk * B_ROWPAD_H + wn*64 + n*16, B_ROWPAD_H);
            #pragma unroll
            for (int m = 0; m < 4; m++)
                #pragma unroll
                for (int n = 0; n < 4; n++)
                    wmma::mma_sync(cf[m][n], af[m], bf[n], cf[m][n]);
        }
    }

    if (tid < BN) s_bias[tid] = b1[(size_t)t * DH + n0 + tid];
    __syncthreads();
    float* sC = (float*)smem;
    #pragma unroll
    for (int m = 0; m < 4; m++)
        #pragma unroll
        for (int n = 0; n < 4; n++)
            wmma::store_matrix_sync(sC + (wm*64 + m*16) * C_ROWPAD + wn*64 + n*16,
                                    cf[m][n], C_ROWPAD, wmma::mem_row_major);
    __syncthreads();

    __half* Hbase = g_H + (size_t)(g_pp[t] + row0) * DH + n0;
    #pragma unroll
    for (int i = 0; i < 32; i++) {
        int idx = tid + i * 128;
        int r = idx >> 5, c4 = idx & 31;
        float4 v = *(float4*)(sC + r * C_ROWPAD + c4 * 4);
        v.x = gelu_exact(v.x + s_bias[c4*4 + 0]);
        v.y = gelu_exact(v.y + s_bias[c4*4 + 1]);
        v.z = gelu_exact(v.z + s_bias[c4*4 + 2]);
        v.w = gelu_exact(v.w + s_bias[c4*4 + 3]);
        __half2 h0 = __floats2half2_rn(v.x, v.y);
        __half2 h1 = __floats2half2_rn(v.z, v.w);
        *(uint2*)(Hbase + (size_t)r * DH + c4 * 4) = make_uint2(*(uint32_t*)&h0, *(uint32_t*)&h1);
    }
}

__global__ __launch_bounds__(128, 2) void gemm2_kernel(const float* __restrict__ b2,
                                                       float* __restrict__ out)
{
    const int t    = blockIdx.z;
    const int cnt  = g_counts[t];
    const int row0 = blockIdx.x * BM;
    if (row0 >= cnt) return;
    const int n0 = blockIdx.y * BN;

    extern __shared__ __half smem[];
    __shared__ float s_bias[BN];
    __shared__ int   s_rows[BM];

    const int tid = threadIdx.x;
    const int wid = tid >> 5;
    const int wm  = wid >> 1, wn = wid & 1;

    if (tid < BM) {
        int r = row0 + tid;
        s_rows[tid] = (r < cnt) ? g_bucket[t][r] : -1;
    }

    const int ar = tid >> 2;
    const int ac = tid & 3;
    const size_t hrow0 = (size_t)(g_pp[t] + row0);
    const __half* aptr[4];
    #pragma unroll
    for (int i = 0; i < 4; i++)
        aptr[i] = g_H + (hrow0 + ar + i * 32) * DH + ac * 8;

    const int br = tid >> 4;
    const int bc = tid & 15;
    const __half* Wt = g_W2h + (size_t)t * DH * DC + n0 + bc * 8;

    const uint32_t smem_u = cvta_s(smem);
    auto fill = [&](int j) {
        const int s = j % STAGES;
        const int k0 = j * BK;
        uint32_t aBase = smem_u + (uint32_t)(s * STAGE_H) * 2u;
        uint32_t bBase = aBase + A_STAGE_H * 2u;
        #pragma unroll
        for (int i = 0; i < 4; i++)
            cp16(aBase + (uint32_t)(ar + i*32) * (A_ROWPAD_H*2u) + (uint32_t)ac * 16u,
                 aptr[i] + k0);
        #pragma unroll
        for (int i = 0; i < 4; i++)
            cp16(bBase + (uint32_t)(br + i*8) * (B_ROWPAD_H*2u) + (uint32_t)bc * 16u,
                 Wt + (size_t)(k0 + br + i*8) * DC);
        CP_COMMIT();
    };

    wmma::fragment<wmma::accumulator, 16, 16, 16, float> cf[4][4];
    #pragma unroll
    for (int i = 0; i < 4; i++)
        #pragma unroll
        for (int j = 0; j < 4; j++)
            wmma::fill_fragment(cf[i][j], 0.f);

    const int NITER = DH / BK;
    fill(0); fill(1); fill(2);

    for (int i = 0; i < NITER; i++) {
        if      (i + 3 <= NITER) { CP_WAIT(2); }
        else if (i + 2 == NITER) { CP_WAIT(1); }
        else                     { CP_WAIT(0); }
        __syncthreads();
        if (i + 3 < NITER) fill(i + 3);

        const __half* sA = smem + (i % STAGES) * STAGE_H;
        const __half* sB = sA + A_STAGE_H;

        #pragma unroll
        for (int kk = 0; kk < BK; kk += 16) {
            wmma::fragment<wmma::matrix_a, 16, 16, 16, __half, wmma::row_major> af[4];
            wmma::fragment<wmma::matrix_b, 16, 16, 16, __half, wmma::row_major> bf[4];
            #pragma unroll
            for (int m = 0; m < 4; m++)
                wmma::load_matrix_sync(af[m], sA + (wm*64 + m*16) * A_ROWPAD_H + kk, A_ROWPAD_H);
            #pragma unroll
            for (int n = 0; n < 4; n++)
                wmma::load_matrix_sync(bf[n], sB + kk * B_ROWPAD_H + wn*64 + n*16, B_ROWPAD_H);
            #pragma unroll
            for (int m = 0; m < 4; m++)
                #pragma unroll
                for (int n = 0; n < 4; n++)
                    wmma::mma_sync(cf[m][n], af[m], bf[n], cf[m][n]);
        }
    }

    if (tid < BN) s_bias[tid] = b2[(size_t)t * DC + n0 + tid];
    __syncthreads();
    float* sC = (float*)smem;
    #pragma unroll
    for (int m = 0; m < 4; m++)
        #pragma unroll
        for (int n = 0; n < 4; n++)
            wmma::store_matrix_sync(sC + (wm*64 + m*16) * C_ROWPAD + wn*64 + n*16,
                                    cf[m][n], C_ROWPAD, wmma::mem_row_major);
    __syncthreads();

    #pragma unroll
    for (int i = 0; i < 32; i++) {
        int idx = tid + i * 128;
        int r = idx >> 5, c4 = idx & 31;
        int tok = s_rows[r];
        if (tok >= 0) {
            float4 v = *(float4*)(sC + r * C_ROWPAD + c4 * 4);
            v.x += s_bias[c4*4 + 0];
            v.y += s_bias[c4*4 + 1];
            v.z += s_bias[c4*4 + 2];
            v.w += s_bias[c4*4 + 3];
            *(float4*)(out + (size_t)tok * DC + n0 + c4 * 4) = v;
        }
    }
}

// ------------------------------- launcher ----------------------------------
extern "C" void kernel_launch(void* const* d_in, const int* in_sizes, int n_in,
                              void* d_out, int out_size)
{
    const float* x            = (const float*)d_in[0];
    const float* pe           = (const float*)d_in[1];
    const float* pwp          = (const float*)d_in[2];
    const float* cwp          = (const float*)d_in[3];
    const float* pos_sigs     = (const float*)d_in[4];
    const float* content_sigs = (const float*)d_in[5];
    const float* W1           = (const float*)d_in[6];
    const float* b1           = (const float*)d_in[7];
    const float* W2           = (const float*)d_in[8];
    const float* b2           = (const float*)d_in[9];
    float* out = (float*)d_out;

    // One-time resource setup (host-side only; no device allocations).
    static cudaStream_t s1 = nullptr, s2 = nullptr;
    static cudaEvent_t  ev0 = nullptr, ev1 = nullptr, ev2 = nullptr;
    static int ready = 0;
    if (!ready) {
        cudaFuncSetAttribute(gemm1_kernel, cudaFuncAttributeMaxDynamicSharedMemorySize, SMEM_DYN);
        cudaFuncSetAttribute(gemm2_kernel, cudaFuncAttributeMaxDynamicSharedMemorySize, SMEM_DYN);
        cudaStreamCreateWithFlags(&s1, cudaStreamNonBlocking);
        cudaStreamCreateWithFlags(&s2, cudaStreamNonBlocking);
        cudaEventCreateWithFlags(&ev0, cudaEventDisableTiming);
        cudaEventCreateWithFlags(&ev1, cudaEventDisableTiming);
        cudaEventCreateWithFlags(&ev2, cudaEventDisableTiming);
        ready = 1;
    }

    __half* w1h; cudaGetSymbolAddress((void**)&w1h, g_W1h);
    __half* w2h; cudaGetSymbolAddress((void**)&w2h, g_W2h);

    // Fork: weight converts run on side streams, overlapping routing (W1)
    // and gemm1 (W2).
    cudaEventRecord(ev0, 0);
    cudaStreamWaitEvent(s1, ev0, 0);
    convert_f2h_kernel<<<NT*DC*DH/8192, 256, 0, s1>>>(W1, w1h);
    cudaEventRecord(ev1, s1);
    cudaStreamWaitEvent(s2, ev0, 0);
    convert_f2h_kernel<<<NT*DH*DC/8192, 256, 0, s2>>>(W2, w2h);
    cudaEventRecord(ev2, s2);

    zero_counts_kernel<<<1, 32>>>();
    routing_kernel<<<NTOK/8, 256>>>(x, pe, pwp, cwp, pos_sigs, content_sigs);
    finalize_kernel<<<1, 1>>>();

    cudaStreamWaitEvent(0, ev1, 0);               // gemm1 needs W1h
    gemm1_kernel<<<dim3(NTOK/BM, DH/BN, NT), 128, SMEM_DYN>>>(b1);

    cudaStreamWaitEvent(0, ev2, 0);               // gemm2 needs W2h
    gemm2_kernel<<<dim3(NTOK/BM, DC/BN, NT), 128, SMEM_DYN>>>(b2, out);
}

// round 8
// speedup vs baseline: 9.5799x; 1.0068x over previous
#include <cuda_runtime.h>
#include <cuda_fp16.h>
#include <mma.h>
#include <math.h>
#include <cstdint>

using namespace nvcuda;

#define NTOK 8192
#define SEQ  512
#define DC   1024
#define DP   64
#define NT   8
#define DH   4096

#define BM 128
#define BN 128
#define BK 32
#define STAGES 4

#define A_ROWPAD_H 40
#define B_ROWPAD_H 136
#define A_STAGE_H (BM * A_ROWPAD_H)
#define B_STAGE_H (BK * B_ROWPAD_H)
#define STAGE_H   (A_STAGE_H + B_STAGE_H)
#define SMEM_DYN  (STAGES * STAGE_H * 2)
#define C_ROWPAD  (BN + 4)

// ------------------------- device scratch (static) -------------------------
__device__ __half g_xh [NTOK * DC];
__device__ __half g_W1h[NT * DC * DH];
__device__ __half g_W2h[NT * DH * DC];
__device__ __half g_H  [(NTOK + NT*BM) * DH];
__device__ int    g_bucket[NT][NTOK];
__device__ int    g_counts[NT];
__device__ int    g_pp[NT];

// ------------------------------- helpers -----------------------------------
__device__ __forceinline__ uint32_t cvta_s(const void* p) {
    uint32_t a;
    asm("{ .reg .u64 t; cvta.to.shared.u64 t, %1; cvt.u32.u64 %0, t; }" : "=r"(a) : "l"(p));
    return a;
}
__device__ __forceinline__ void cp16(uint32_t dst, const void* src) {
    asm volatile("cp.async.cg.shared.global [%0], [%1], 16;" :: "r"(dst), "l"(src));
}
#define CP_COMMIT() asm volatile("cp.async.commit_group;" ::: "memory")
#define CP_WAIT(N)  asm volatile("cp.async.wait_group %0;" :: "n"(N) : "memory")

__device__ __forceinline__ float gelu_exact(float v) {
    return 0.5f * v * (1.0f + erff(v * 0.70710678118654752f));
}

// ------------------------------ small kernels ------------------------------
__global__ void zero_counts_kernel() {
    if (threadIdx.x < NT) g_counts[threadIdx.x] = 0;
}
__global__ void finalize_kernel() {
    int off = 0;
    for (int t = 0; t < NT; t++) {
        g_pp[t] = off;
        off += ((g_counts[t] + BM - 1) / BM) * BM;
    }
}

// fp32 -> fp16 convert: 8192 floats per 256-thread block, MLP=8.
__global__ __launch_bounds__(256) void convert_f2h_kernel(const float* __restrict__ src,
                                                          __half* __restrict__ dst) {
    const size_t base = (size_t)blockIdx.x * 8192;
    const int tid = threadIdx.x;
    float4 v[8];
    #pragma unroll
    for (int i = 0; i < 8; i++)
        v[i] = *(const float4*)(src + base + (size_t)(i*256 + tid) * 4);
    #pragma unroll
    for (int i = 0; i < 8; i++) {
        __half2 h0 = __floats2half2_rn(v[i].x, v[i].y);
        __half2 h1 = __floats2half2_rn(v[i].z, v[i].w);
        *(uint2*)(dst + base + (size_t)(i*256 + tid) * 4) =
            make_uint2(*(uint32_t*)&h0, *(uint32_t*)&h1);
    }
}

// ------------------- routing (+ fused x -> fp16 convert) -------------------
// float2-vectorized inner loop: per 2 elements 1 LDG.64 + 1 STG.32 + 8 LDS.64
// + 16 FFMA (vs 36 issue slots before).
__global__ void routing_kernel(const float* __restrict__ x,
                               const float* __restrict__ pe,
                               const float* __restrict__ pwp,
                               const float* __restrict__ cwp,
                               const float* __restrict__ pos_sigs,
                               const float* __restrict__ content_sigs)
{
    __shared__ float s_csig[NT][DC];
    __shared__ float s_psig[NT][DP];
    int tid = threadIdx.x;
    for (int i = tid; i < NT*DC; i += blockDim.x) {
        float v = content_sigs[i];
        ((float*)s_csig)[i] = (v > 0.f) ? 1.f : ((v < 0.f) ? -1.f : 0.f);
    }
    for (int i = tid; i < NT*DP; i += blockDim.x) {
        float v = pos_sigs[i];
        ((float*)s_psig)[i] = (v > 0.f) ? 1.f : ((v < 0.f) ? -1.f : 0.f);
    }
    __syncthreads();

    float pw = 1.f / (1.f + expf(-pwp[0]));
    float cw = 1.f / (1.f + expf(-cwp[0]));
    float tot = pw + cw;
    pw /= tot; cw /= tot;

    int token = (blockIdx.x * blockDim.x + tid) >> 5;
    int lane  = tid & 31;
    if (token >= NTOK) return;
    int s = token % SEQ;

    float accx[NT], accy[NT];
    #pragma unroll
    for (int t = 0; t < NT; t++) { accx[t] = 0.f; accy[t] = 0.f; }

    const float2* xr2 = (const float2*)(x + (size_t)token * DC);
    __half2* xh2 = (__half2*)(g_xh + (size_t)token * DC);
    #pragma unroll 4
    for (int j2 = lane; j2 < DC/2; j2 += 32) {
        float2 xv = xr2[j2];
        xh2[j2] = __floats2half2_rn(xv.x, xv.y);          // fused convert
        #pragma unroll
        for (int t = 0; t < NT; t++) {
            float2 sv = *(const float2*)&s_csig[t][j2*2];
            accx[t] += xv.x * sv.x;
            accy[t] += xv.y * sv.y;
        }
    }

    float acc[NT];
    #pragma unroll
    for (int t = 0; t < NT; t++) acc[t] = (accx[t] + accy[t]) * cw;

    for (int j = lane; j < DP; j += 32) {
        float pv = pe[s*DP + j] * pw;
        #pragma unroll
        for (int t = 0; t < NT; t++) acc[t] += pv * s_psig[t][j];
    }
    #pragma unroll
    for (int t = 0; t < NT; t++) {
        #pragma unroll
        for (int o = 16; o > 0; o >>= 1)
            acc[t] += __shfl_xor_sync(0xffffffffu, acc[t], o);
    }
    if (lane == 0) {
        int best = 0; float bv = acc[0];
        #pragma unroll
        for (int t = 1; t < NT; t++)
            if (acc[t] > bv) { bv = acc[t]; best = t; }
        int pos = atomicAdd(&g_counts[best], 1);
        g_bucket[best][pos] = token;
    }
}

// ===========================================================================
// fp16 HMMA GEMMs (proven core): 128 threads, 2x2 warps of 64x64,
// 4-stage cp.async, one barrier per K-iter, 2 CTAs/SM.
// ===========================================================================

__global__ __launch_bounds__(128, 2) void gemm1_kernel(const float* __restrict__ b1)
{
    const int t    = blockIdx.z;
    const int cnt  = g_counts[t];
    const int row0 = blockIdx.x * BM;
    if (row0 >= cnt) return;
    const int n0 = blockIdx.y * BN;

    extern __shared__ __half smem[];
    __shared__ float s_bias[BN];

    const int tid = threadIdx.x;
    const int wid = tid >> 5;
    const int wm  = wid >> 1, wn = wid & 1;

    s_bias[tid] = b1[(size_t)t * DH + n0 + tid];   // preload, hidden under mainloop

    const int ar = tid >> 2;
    const int ac = tid & 3;
    const __half* aptr[4];
    #pragma unroll
    for (int i = 0; i < 4; i++) {
        int idx = row0 + ar + i * 32;
        if (idx > cnt - 1) idx = cnt - 1;
        aptr[i] = g_xh + (size_t)g_bucket[t][idx] * DC + ac * 8;
    }
    const int br = tid >> 4;
    const int bc = tid & 15;
    const __half* Wt = g_W1h + (size_t)t * DC * DH + n0 + bc * 8;

    const uint32_t smem_u = cvta_s(smem);
    auto fill = [&](int j) {
        const int s = j % STAGES;
        const int k0 = j * BK;
        uint32_t aBase = smem_u + (uint32_t)(s * STAGE_H) * 2u;
        uint32_t bBase = aBase + A_STAGE_H * 2u;
        #pragma unroll
        for (int i = 0; i < 4; i++)
            cp16(aBase + (uint32_t)(ar + i*32) * (A_ROWPAD_H*2u) + (uint32_t)ac * 16u,
                 aptr[i] + k0);
        #pragma unroll
        for (int i = 0; i < 4; i++)
            cp16(bBase + (uint32_t)(br + i*8) * (B_ROWPAD_H*2u) + (uint32_t)bc * 16u,
                 Wt + (size_t)(k0 + br + i*8) * DH);
        CP_COMMIT();
    };

    wmma::fragment<wmma::accumulator, 16, 16, 16, float> cf[4][4];
    #pragma unroll
    for (int i = 0; i < 4; i++)
        #pragma unroll
        for (int j = 0; j < 4; j++)
            wmma::fill_fragment(cf[i][j], 0.f);

    const int NITER = DC / BK;
    fill(0); fill(1); fill(2);

    for (int i = 0; i < NITER; i++) {
        if      (i + 3 <= NITER) { CP_WAIT(2); }
        else if (i + 2 == NITER) { CP_WAIT(1); }
        else                     { CP_WAIT(0); }
        __syncthreads();
        if (i + 3 < NITER) fill(i + 3);

        const __half* sA = smem + (i % STAGES) * STAGE_H;
        const __half* sB = sA + A_STAGE_H;

        #pragma unroll
        for (int kk = 0; kk < BK; kk += 16) {
            wmma::fragment<wmma::matrix_a, 16, 16, 16, __half, wmma::row_major> af[4];
            wmma::fragment<wmma::matrix_b, 16, 16, 16, __half, wmma::row_major> bf[4];
            #pragma unroll
            for (int m = 0; m < 4; m++)
                wmma::load_matrix_sync(af[m], sA + (wm*64 + m*16) * A_ROWPAD_H + kk, A_ROWPAD_H);
            #pragma unroll
            for (int n = 0; n < 4; n++)
                wmma::load_matrix_sync(bf[n], sB + kk * B_ROWPAD_H + wn*64 + n*16, B_ROWPAD_H);
            #pragma unroll
            for (int m = 0; m < 4; m++)
                #pragma unroll
                for (int n = 0; n < 4; n++)
                    wmma::mma_sync(cf[m][n], af[m], bf[n], cf[m][n]);
        }
    }

    __syncthreads();
    float* sC = (float*)smem;
    #pragma unroll
    for (int m = 0; m < 4; m++)
        #pragma unroll
        for (int n = 0; n < 4; n++)
            wmma::store_matrix_sync(sC + (wm*64 + m*16) * C_ROWPAD + wn*64 + n*16,
                                    cf[m][n], C_ROWPAD, wmma::mem_row_major);
    __syncthreads();

    __half* Hbase = g_H + (size_t)(g_pp[t] + row0) * DH + n0;
    #pragma unroll
    for (int i = 0; i < 32; i++) {
        int idx = tid + i * 128;
        int r = idx >> 5, c4 = idx & 31;
        float4 v = *(float4*)(sC + r * C_ROWPAD + c4 * 4);
        v.x = gelu_exact(v.x + s_bias[c4*4 + 0]);
        v.y = gelu_exact(v.y + s_bias[c4*4 + 1]);
        v.z = gelu_exact(v.z + s_bias[c4*4 + 2]);
        v.w = gelu_exact(v.w + s_bias[c4*4 + 3]);
        __half2 h0 = __floats2half2_rn(v.x, v.y);
        __half2 h1 = __floats2half2_rn(v.z, v.w);
        *(uint2*)(Hbase + (size_t)r * DH + c4 * 4) = make_uint2(*(uint32_t*)&h0, *(uint32_t*)&h1);
    }
}

__global__ __launch_bounds__(128, 2) void gemm2_kernel(const float* __restrict__ b2,
                                                       float* __restrict__ out)
{
    const int t    = blockIdx.z;
    const int cnt  = g_counts[t];
    const int row0 = blockIdx.x * BM;
    if (row0 >= cnt) return;
    const int n0 = blockIdx.y * BN;

    extern __shared__ __half smem[];
    __shared__ float s_bias[BN];
    __shared__ int   s_rows[BM];

    const int tid = threadIdx.x;
    const int wid = tid >> 5;
    const int wm  = wid >> 1, wn = wid & 1;

    s_bias[tid] = b2[(size_t)t * DC + n0 + tid];
    {
        int r = row0 + tid;
        s_rows[tid] = (r < cnt) ? g_bucket[t][r] : -1;
    }

    const int ar = tid >> 2;
    const int ac = tid & 3;
    const size_t hrow0 = (size_t)(g_pp[t] + row0);
    const __half* aptr[4];
    #pragma unroll
    for (int i = 0; i < 4; i++)
        aptr[i] = g_H + (hrow0 + ar + i * 32) * DH + ac * 8;

    const int br = tid >> 4;
    const int bc = tid & 15;
    const __half* Wt = g_W2h + (size_t)t * DH * DC + n0 + bc * 8;

    const uint32_t smem_u = cvta_s(smem);
    auto fill = [&](int j) {
        const int s = j % STAGES;
        const int k0 = j * BK;
        uint32_t aBase = smem_u + (uint32_t)(s * STAGE_H) * 2u;
        uint32_t bBase = aBase + A_STAGE_H * 2u;
        #pragma unroll
        for (int i = 0; i < 4; i++)
            cp16(aBase + (uint32_t)(ar + i*32) * (A_ROWPAD_H*2u) + (uint32_t)ac * 16u,
                 aptr[i] + k0);
        #pragma unroll
        for (int i = 0; i < 4; i++)
            cp16(bBase + (uint32_t)(br + i*8) * (B_ROWPAD_H*2u) + (uint32_t)bc * 16u,
                 Wt + (size_t)(k0 + br + i*8) * DC);
        CP_COMMIT();
    };

    wmma::fragment<wmma::accumulator, 16, 16, 16, float> cf[4][4];
    #pragma unroll
    for (int i = 0; i < 4; i++)
        #pragma unroll
        for (int j = 0; j < 4; j++)
            wmma::fill_fragment(cf[i][j], 0.f);

    const int NITER = DH / BK;
    fill(0); fill(1); fill(2);

    for (int i = 0; i < NITER; i++) {
        if      (i + 3 <= NITER) { CP_WAIT(2); }
        else if (i + 2 == NITER) { CP_WAIT(1); }
        else                     { CP_WAIT(0); }
        __syncthreads();
        if (i + 3 < NITER) fill(i + 3);

        const __half* sA = smem + (i % STAGES) * STAGE_H;
        const __half* sB = sA + A_STAGE_H;

        #pragma unroll
        for (int kk = 0; kk < BK; kk += 16) {
            wmma::fragment<wmma::matrix_a, 16, 16, 16, __half, wmma::row_major> af[4];
            wmma::fragment<wmma::matrix_b, 16, 16, 16, __half, wmma::row_major> bf[4];
            #pragma unroll
            for (int m = 0; m < 4; m++)
                wmma::load_matrix_sync(af[m], sA + (wm*64 + m*16) * A_ROWPAD_H + kk, A_ROWPAD_H);
            #pragma unroll
            for (int n = 0; n < 4; n++)
                wmma::load_matrix_sync(bf[n], sB + kk * B_ROWPAD_H + wn*64 + n*16, B_ROWPAD_H);
            #pragma unroll
            for (int m = 0; m < 4; m++)
                #pragma unroll
                for (int n = 0; n < 4; n++)
                    wmma::mma_sync(cf[m][n], af[m], bf[n], cf[m][n]);
        }
    }

    __syncthreads();
    float* sC = (float*)smem;
    #pragma unroll
    for (int m = 0; m < 4; m++)
        #pragma unroll
        for (int n = 0; n < 4; n++)
            wmma::store_matrix_sync(sC + (wm*64 + m*16) * C_ROWPAD + wn*64 + n*16,
                                    cf[m][n], C_ROWPAD, wmma::mem_row_major);
    __syncthreads();

    #pragma unroll
    for (int i = 0; i < 32; i++) {
        int idx = tid + i * 128;
        int r = idx >> 5, c4 = idx & 31;
        int tok = s_rows[r];
        if (tok >= 0) {
            float4 v = *(float4*)(sC + r * C_ROWPAD + c4 * 4);
            v.x += s_bias[c4*4 + 0];
            v.y += s_bias[c4*4 + 1];
            v.z += s_bias[c4*4 + 2];
            v.w += s_bias[c4*4 + 3];
            *(float4*)(out + (size_t)tok * DC + n0 + c4 * 4) = v;
        }
    }
}

// ------------------------------- launcher ----------------------------------
extern "C" void kernel_launch(void* const* d_in, const int* in_sizes, int n_in,
                              void* d_out, int out_size)
{
    const float* x            = (const float*)d_in[0];
    const float* pe           = (const float*)d_in[1];
    const float* pwp          = (const float*)d_in[2];
    const float* cwp          = (const float*)d_in[3];
    const float* pos_sigs     = (const float*)d_in[4];
    const float* content_sigs = (const float*)d_in[5];
    const float* W1           = (const float*)d_in[6];
    const float* b1           = (const float*)d_in[7];
    const float* W2           = (const float*)d_in[8];
    const float* b2           = (const float*)d_in[9];
    float* out = (float*)d_out;

    static cudaStream_t s1 = nullptr, s2 = nullptr;
    static cudaEvent_t  ev0 = nullptr, ev1a = nullptr, ev1b = nullptr,
                        ev2a = nullptr, ev2b = nullptr;
    static int ready = 0;
    if (!ready) {
        cudaFuncSetAttribute(gemm1_kernel, cudaFuncAttributeMaxDynamicSharedMemorySize, SMEM_DYN);
        cudaFuncSetAttribute(gemm2_kernel, cudaFuncAttributeMaxDynamicSharedMemorySize, SMEM_DYN);
        cudaStreamCreateWithFlags(&s1, cudaStreamNonBlocking);
        cudaStreamCreateWithFlags(&s2, cudaStreamNonBlocking);
        cudaEventCreateWithFlags(&ev0,  cudaEventDisableTiming);
        cudaEventCreateWithFlags(&ev1a, cudaEventDisableTiming);
        cudaEventCreateWithFlags(&ev1b, cudaEventDisableTiming);
        cudaEventCreateWithFlags(&ev2a, cudaEventDisableTiming);
        cudaEventCreateWithFlags(&ev2b, cudaEventDisableTiming);
        ready = 1;
    }

    __half* w1h; cudaGetSymbolAddress((void**)&w1h, g_W1h);
    __half* w2h; cudaGetSymbolAddress((void**)&w2h, g_W2h);

    const int WBLK  = NT*DC*DH/8192;          // 4096 blocks per weight tensor
    const int HALF  = WBLK/2;
    const size_t HOFF = (size_t)HALF * 8192;

    // Fork both streams; each converts half of W1 first (W1h ready ASAP),
    // then half of W2 (joined before gemm2, fully hidden under gemm1).
    cudaEventRecord(ev0, 0);
    cudaStreamWaitEvent(s1, ev0, 0);
    cudaStreamWaitEvent(s2, ev0, 0);

    convert_f2h_kernel<<<HALF, 256, 0, s1>>>(W1,        w1h);
    convert_f2h_kernel<<<HALF, 256, 0, s2>>>(W1 + HOFF, w1h + HOFF);
    cudaEventRecord(ev1a, s1);
    cudaEventRecord(ev1b, s2);

    convert_f2h_kernel<<<HALF, 256, 0, s1>>>(W2,        w2h);
    convert_f2h_kernel<<<HALF, 256, 0, s2>>>(W2 + HOFF, w2h + HOFF);
    cudaEventRecord(ev2a, s1);
    cudaEventRecord(ev2b, s2);

    zero_counts_kernel<<<1, 32>>>();
    routing_kernel<<<NTOK/8, 256>>>(x, pe, pwp, cwp, pos_sigs, content_sigs);
    finalize_kernel<<<1, 1>>>();

    cudaStreamWaitEvent(0, ev1a, 0);
    cudaStreamWaitEvent(0, ev1b, 0);
    gemm1_kernel<<<dim3(NTOK/BM, DH/BN, NT), 128, SMEM_DYN>>>(b1);

    cudaStreamWaitEvent(0, ev2a, 0);
    cudaStreamWaitEvent(0, ev2b, 0);
    gemm2_kernel<<<dim3(NTOK/BM, DC/BN, NT), 128, SMEM_DYN>>>(b2, out);
}